// round 6
// baseline (speedup 1.0000x reference)
#include <cuda_runtime.h>
#include <cuda_bf16.h>
#include <math.h>

// ---------------------------------------------------------------------------
// Problem constants (CoconBlock: B=2, S=1024, Sc=256, D=768, H=12, dh=64)
// ---------------------------------------------------------------------------
constexpr int cD   = 768;
constexpr int cH   = 12;
constexpr int cDH  = 64;
constexpr int cB   = 2;
constexpr int cS   = 1024;
constexpr int cSC  = 256;
constexpr int cND  = cS + 1;          // 1025 queries per batch (sos + seq)
constexpr int cNS  = cSC + cND;       // 1281 keys per batch
constexpr int cM   = cB * cND;        // 2050 rows in main activation
constexpr int cMC  = cB * cSC;        // 512 context rows
constexpr int cBH  = cB * cH;         // 24 (batch, head) pairs

// ---------------------------------------------------------------------------
// Scratch (static __device__ arrays; no allocation anywhere)
// ---------------------------------------------------------------------------
__device__ float g_H  [(size_t)cM * cD];          // h  (pre-LN residual stream)
__device__ float g_HL [(size_t)cM * cD];          // ln1(h)
__device__ float g_QKV[(size_t)cM * 3 * cD];      // qkv
__device__ float g_CKV[(size_t)cMC * 2 * cD];     // context k/v
__device__ float g_Q  [(size_t)cBH * cND * cDH];  // per-head Q
__device__ float g_K  [(size_t)cBH * cNS * cDH];  // per-head K (ctx ++ seq)
__device__ float g_V  [(size_t)cBH * cNS * cDH];  // per-head V
__device__ float g_S  [(size_t)cBH * cND * cNS];  // attention scores / probs (126 MB)
__device__ float g_A  [(size_t)cM * cD];          // merged-head attention output
__device__ float g_H2 [(size_t)cM * cD];          // h + attn_proj
__device__ float g_HL2[(size_t)cM * cD];          // ln2(h2)
__device__ float g_FC [(size_t)cM * 4 * cD];      // gelu(fc)

// ---------------------------------------------------------------------------
// Helpers
// ---------------------------------------------------------------------------
__device__ __forceinline__ float gelu_new(float x) {
    float x3 = x * x * x;
    return 0.5f * x * (1.0f + tanhf(0.7978845608028654f * (x + 0.044715f * x3)));
}

// ---------------------------------------------------------------------------
// LayerNorm (optionally fused with the sos-concat gather).
// One block per row, 256 threads, 3 elements/thread (D = 768).
// concat==1: src rows come from {sos | x}, also writes Hout.
// concat==0: src = in + r*768, writes only HLout.
// ---------------------------------------------------------------------------
__global__ __launch_bounds__(256) void ln_kernel(
    const float* __restrict__ in, const float* __restrict__ sos,
    const float* __restrict__ gamma, const float* __restrict__ beta,
    float* __restrict__ Hout, float* __restrict__ HLout, int concat)
{
    int r   = blockIdx.x;
    int tid = threadIdx.x;
    const float* src;
    if (concat) {
        int b = r / cND, t = r % cND;
        src = (t == 0) ? sos : in + ((size_t)b * cS + (t - 1)) * cD;
    } else {
        src = in + (size_t)r * cD;
    }
    float v0 = src[tid], v1 = src[tid + 256], v2 = src[tid + 512];
    float s  = v0 + v1 + v2;
    float ss = v0 * v0 + v1 * v1 + v2 * v2;

    __shared__ float sb[8], sb2[8];
    #pragma unroll
    for (int o = 16; o; o >>= 1) {
        s  += __shfl_xor_sync(0xffffffffu, s,  o);
        ss += __shfl_xor_sync(0xffffffffu, ss, o);
    }
    int lane = tid & 31, w = tid >> 5;
    if (lane == 0) { sb[w] = s; sb2[w] = ss; }
    __syncthreads();
    if (tid == 0) {
        float a = 0.f, c = 0.f;
        #pragma unroll
        for (int i = 0; i < 8; i++) { a += sb[i]; c += sb2[i]; }
        sb[0] = a; sb2[0] = c;
    }
    __syncthreads();
    float mean = sb[0] * (1.0f / 768.0f);
    float var  = sb2[0] * (1.0f / 768.0f) - mean * mean;
    float inv  = rsqrtf(var + 1e-5f);

    if (concat) {
        float* hr = Hout + (size_t)r * cD;
        hr[tid] = v0; hr[tid + 256] = v1; hr[tid + 512] = v2;
    }
    float* hlr = HLout + (size_t)r * cD;
    hlr[tid      ] = (v0 - mean) * inv * gamma[tid      ] + beta[tid      ];
    hlr[tid + 256] = (v1 - mean) * inv * gamma[tid + 256] + beta[tid + 256];
    hlr[tid + 512] = (v2 - mean) * inv * gamma[tid + 512] + beta[tid + 512];
}

// ---------------------------------------------------------------------------
// Generic SGEMM  C[M,N] = A[M,K] @ B[K,N] + bias  (+ epilogue)
// Requires: N % BN == 0, K % BK == 0, BM*BK == BN*BK == 4*THREADS.
// mode: 0 = none, 1 = gelu_new, 2 = + R[r,n], 3 = + R[r,n] then write to
//       out with the sos row dropped (r -> b*1024 + t-1, skip t==0).
// ---------------------------------------------------------------------------
template<int BM, int BN, int BK, int TM, int TN>
__global__ __launch_bounds__((BM / TM) * (BN / TN)) void sgemm_k(
    const float* __restrict__ A, const float* __restrict__ B,
    const float* __restrict__ bias, const float* __restrict__ R,
    float* __restrict__ C, int M, int N, int K, int mode)
{
    constexpr int THREADS = (BM / TM) * (BN / TN);
    static_assert(BM * BK == 4 * THREADS && BN * BK == 4 * THREADS, "load map");
    __shared__ float As[BK][BM];
    __shared__ float Bs[BK][BN];

    const int tid  = threadIdx.x;
    const int row0 = blockIdx.y * BM;
    const int col0 = blockIdx.x * BN;

    const int arow = tid / (BK / 4);
    const int acol = (tid % (BK / 4)) * 4;
    const int brow = tid / (BN / 4);
    const int bcol = (tid % (BN / 4)) * 4;

    constexpr int TX = BN / TN;
    const int tx = tid % TX, ty = tid / TX;

    const bool aval = (row0 + arow) < M;
    const float* Ap = A + (size_t)(row0 + arow) * K + acol;
    const float* Bp = B + (size_t)brow * N + col0 + bcol;

    float acc[TM][TN];
    #pragma unroll
    for (int i = 0; i < TM; i++)
        #pragma unroll
        for (int j = 0; j < TN; j++) acc[i][j] = 0.f;

    for (int kt = 0; kt < K; kt += BK) {
        float4 a4 = aval ? *(const float4*)Ap : make_float4(0.f, 0.f, 0.f, 0.f);
        float4 b4 = *(const float4*)Bp;
        __syncthreads();
        As[acol + 0][arow] = a4.x; As[acol + 1][arow] = a4.y;
        As[acol + 2][arow] = a4.z; As[acol + 3][arow] = a4.w;
        *(float4*)&Bs[brow][bcol] = b4;
        __syncthreads();
        #pragma unroll
        for (int k = 0; k < BK; k++) {
            float ar[TM], br[TN];
            #pragma unroll
            for (int i = 0; i < TM; i += 4)
                *(float4*)&ar[i] = *(const float4*)&As[k][ty * TM + i];
            #pragma unroll
            for (int j = 0; j < TN; j += 4)
                *(float4*)&br[j] = *(const float4*)&Bs[k][tx * TN + j];
            #pragma unroll
            for (int i = 0; i < TM; i++)
                #pragma unroll
                for (int j = 0; j < TN; j++)
                    acc[i][j] += ar[i] * br[j];
        }
        Ap += BK;
        Bp += (size_t)BK * N;
    }

    #pragma unroll
    for (int i = 0; i < TM; i++) {
        int r = row0 + ty * TM + i;
        if (r >= M) continue;
        float* crow;
        if (mode == 3) {
            int bb = r / cND, t = r % cND;
            if (t == 0) continue;                       // drop sos row
            crow = C + ((size_t)(bb * cS + (t - 1))) * N;
        } else {
            crow = C + (size_t)r * N;
        }
        #pragma unroll
        for (int j = 0; j < TN; j++) {
            int c = col0 + tx * TN + j;
            float v = acc[i][j] + bias[c];
            if (mode == 1)      v = gelu_new(v);
            else if (mode >= 2) v += R[(size_t)r * N + c];
            crow[c] = v;
        }
    }
}

// ---------------------------------------------------------------------------
// Head gathers: QKV/CKV -> per-head contiguous Q/K/V buffers
// ---------------------------------------------------------------------------
__global__ void gather_q(const float* __restrict__ QKV, float* __restrict__ Q)
{
    int idx = blockIdx.x * blockDim.x + threadIdx.x;
    if (idx >= cBH * cND * cDH) return;
    int d    = idx & (cDH - 1);
    int rest = idx >> 6;
    int t    = rest % cND;
    int bh   = rest / cND;
    int b = bh / cH, h = bh % cH;
    Q[idx] = QKV[((size_t)(b * cND + t)) * (3 * cD) + h * cDH + d];
}

__global__ void gather_kv(const float* __restrict__ QKV, const float* __restrict__ CKV,
                          float* __restrict__ Kb, float* __restrict__ Vb)
{
    int idx = blockIdx.x * blockDim.x + threadIdx.x;
    if (idx >= cBH * cNS * cDH) return;
    int d    = idx & (cDH - 1);
    int rest = idx >> 6;
    int j    = rest % cNS;
    int bh   = rest / cNS;
    int b = bh / cH, h = bh % cH;
    float kv, vv;
    if (j < cSC) {
        size_t base = ((size_t)(b * cSC + j)) * (2 * cD) + h * cDH + d;
        kv = CKV[base];
        vv = CKV[base + cD];
    } else {
        int t = j - cSC;
        size_t base = ((size_t)(b * cND + t)) * (3 * cD) + h * cDH + d;
        kv = QKV[base + cD];
        vv = QKV[base + 2 * cD];
    }
    Kb[idx] = kv;
    Vb[idx] = vv;
}

// ---------------------------------------------------------------------------
// Scores: S[bh,m,n] = (Q[bh,m,:] . K[bh,n,:]) / 8  if n <= m+Sc else -10000
// Tiles 64x64 over (m,n), full dh=64 in shared memory. Stride-65 smem kills
// the transpose-store bank conflicts.
// ---------------------------------------------------------------------------
__global__ __launch_bounds__(256) void attn_scores(
    const float* __restrict__ Q, const float* __restrict__ Kb, float* __restrict__ S)
{
    __shared__ float Qs[64][65];   // [d][m]
    __shared__ float Ks[64][65];   // [d][n]
    int bh = blockIdx.z;
    int m0 = blockIdx.y * 64;
    int n0 = blockIdx.x * 64;
    int tid = threadIdx.x;
    int lr = tid >> 4;
    int lc = (tid & 15) * 4;
    const float* Qb  = Q  + ((size_t)bh * cND + m0) * cDH;
    const float* Kbb = Kb + ((size_t)bh * cNS + n0) * cDH;

    #pragma unroll
    for (int it = 0; it < 4; it++) {
        int m = lr + it * 16;
        float4 v = make_float4(0.f, 0.f, 0.f, 0.f);
        if (m0 + m < cND) v = *(const float4*)(Qb + (size_t)m * cDH + lc);
        Qs[lc + 0][m] = v.x; Qs[lc + 1][m] = v.y;
        Qs[lc + 2][m] = v.z; Qs[lc + 3][m] = v.w;
        float4 w = make_float4(0.f, 0.f, 0.f, 0.f);
        if (n0 + m < cNS) w = *(const float4*)(Kbb + (size_t)m * cDH + lc);
        Ks[lc + 0][m] = w.x; Ks[lc + 1][m] = w.y;
        Ks[lc + 2][m] = w.z; Ks[lc + 3][m] = w.w;
    }
    __syncthreads();

    int tx = tid & 15, ty = tid >> 4;
    float acc[4][4] = {};
    #pragma unroll 8
    for (int k = 0; k < 64; k++) {
        float a0 = Qs[k][ty * 4 + 0], a1 = Qs[k][ty * 4 + 1];
        float a2 = Qs[k][ty * 4 + 2], a3 = Qs[k][ty * 4 + 3];
        float b0 = Ks[k][tx * 4 + 0], b1 = Ks[k][tx * 4 + 1];
        float b2 = Ks[k][tx * 4 + 2], b3 = Ks[k][tx * 4 + 3];
        acc[0][0] += a0 * b0; acc[0][1] += a0 * b1; acc[0][2] += a0 * b2; acc[0][3] += a0 * b3;
        acc[1][0] += a1 * b0; acc[1][1] += a1 * b1; acc[1][2] += a1 * b2; acc[1][3] += a1 * b3;
        acc[2][0] += a2 * b0; acc[2][1] += a2 * b1; acc[2][2] += a2 * b2; acc[2][3] += a2 * b3;
        acc[3][0] += a3 * b0; acc[3][1] += a3 * b1; acc[3][2] += a3 * b2; acc[3][3] += a3 * b3;
    }

    const float scale = 0.125f;   // 1/sqrt(64)
    #pragma unroll
    for (int i = 0; i < 4; i++) {
        int m = m0 + ty * 4 + i;
        if (m >= cND) continue;
        float* Sr = S + ((size_t)bh * cND + m) * cNS;
        #pragma unroll
        for (int j = 0; j < 4; j++) {
            int n = n0 + tx * 4 + j;
            if (n >= cNS) continue;
            Sr[n] = (n <= m + cSC) ? acc[i][j] * scale : -10000.0f;
        }
    }
}

// ---------------------------------------------------------------------------
// Row softmax over ns=1281, one block per (bh, query) row; values stay in
// registers across the three phases (max, exp+sum, normalize).
// ---------------------------------------------------------------------------
__global__ __launch_bounds__(256) void softmax_rows(float* __restrict__ S)
{
    size_t row = blockIdx.x;
    float* p = S + row * (size_t)cNS;
    int tid = threadIdx.x;
    float vals[6];
    float mx = -3.4e38f;
    #pragma unroll
    for (int it = 0; it < 6; it++) {
        int i = tid + it * 256;
        float v = (i < cNS) ? p[i] : -3.4e38f;
        vals[it] = v;
        mx = fmaxf(mx, v);
    }
    __shared__ float sb[8];
    #pragma unroll
    for (int o = 16; o; o >>= 1) mx = fmaxf(mx, __shfl_xor_sync(0xffffffffu, mx, o));
    if ((tid & 31) == 0) sb[tid >> 5] = mx;
    __syncthreads();
    if (tid < 32) {
        float m2 = (tid < 8) ? sb[tid] : -3.4e38f;
        #pragma unroll
        for (int o = 4; o; o >>= 1) m2 = fmaxf(m2, __shfl_xor_sync(0xffffffffu, m2, o));
        if (tid == 0) sb[0] = m2;
    }
    __syncthreads();
    float bmax = sb[0];
    __syncthreads();

    float s = 0.f;
    #pragma unroll
    for (int it = 0; it < 6; it++) {
        int i = tid + it * 256;
        if (i < cNS) {
            float e = __expf(vals[it] - bmax);
            vals[it] = e;
            s += e;
        }
    }
    #pragma unroll
    for (int o = 16; o; o >>= 1) s += __shfl_xor_sync(0xffffffffu, s, o);
    if ((tid & 31) == 0) sb[tid >> 5] = s;
    __syncthreads();
    if (tid < 32) {
        float s2 = (tid < 8) ? sb[tid] : 0.f;
        #pragma unroll
        for (int o = 4; o; o >>= 1) s2 += __shfl_xor_sync(0xffffffffu, s2, o);
        if (tid == 0) sb[0] = s2;
    }
    __syncthreads();
    float inv = 1.0f / sb[0];
    #pragma unroll
    for (int it = 0; it < 6; it++) {
        int i = tid + it * 256;
        if (i < cNS) p[i] = vals[it] * inv;
    }
}

// ---------------------------------------------------------------------------
// AV: O[bh,m,d] = sum_j P[bh,m,j] * V[bh,j,d]; writes directly into the
// merged-head layout A[(b*nd+m), h*64+d] so no extra transpose is needed.
// ---------------------------------------------------------------------------
__global__ __launch_bounds__(256) void attn_av(
    const float* __restrict__ P, const float* __restrict__ Vb, float* __restrict__ A)
{
    __shared__ float Ps[16][65];   // [k][m]
    __shared__ float Vs[16][64];   // [k][d]
    int bh = blockIdx.y;
    int b = bh / cH, h = bh % cH;
    int m0 = blockIdx.x * 64;
    int tid = threadIdx.x;
    int pr = tid >> 2, pc = (tid & 3) * 4;
    int vr = tid >> 4, vc = (tid & 15) * 4;
    int tx = tid & 15, ty = tid >> 4;

    const float* Pb  = P  + ((size_t)bh * cND + m0) * cNS;
    const float* Vbb = Vb + (size_t)bh * cNS * cDH;
    const bool pval = (m0 + pr) < cND;

    float acc[4][4] = {};
    for (int kt = 0; kt < cNS; kt += 16) {
        float p0 = 0.f, p1 = 0.f, p2 = 0.f, p3 = 0.f;
        if (pval) {
            const float* pp = Pb + (size_t)pr * cNS;   // rows are odd-length: scalar loads
            int kk = kt + pc;
            if (kk + 3 < cNS) { p0 = pp[kk]; p1 = pp[kk + 1]; p2 = pp[kk + 2]; p3 = pp[kk + 3]; }
            else {
                if (kk     < cNS) p0 = pp[kk];
                if (kk + 1 < cNS) p1 = pp[kk + 1];
                if (kk + 2 < cNS) p2 = pp[kk + 2];
            }
        }
        float4 vv = make_float4(0.f, 0.f, 0.f, 0.f);
        if (kt + vr < cNS) vv = *(const float4*)(Vbb + (size_t)(kt + vr) * cDH + vc);
        __syncthreads();
        Ps[pc + 0][pr] = p0; Ps[pc + 1][pr] = p1;
        Ps[pc + 2][pr] = p2; Ps[pc + 3][pr] = p3;
        *(float4*)&Vs[vr][vc] = vv;
        __syncthreads();
        #pragma unroll
        for (int k = 0; k < 16; k++) {
            float a0 = Ps[k][ty * 4 + 0], a1 = Ps[k][ty * 4 + 1];
            float a2 = Ps[k][ty * 4 + 2], a3 = Ps[k][ty * 4 + 3];
            float4 bb = *(const float4*)&Vs[k][tx * 4];
            acc[0][0] += a0 * bb.x; acc[0][1] += a0 * bb.y; acc[0][2] += a0 * bb.z; acc[0][3] += a0 * bb.w;
            acc[1][0] += a1 * bb.x; acc[1][1] += a1 * bb.y; acc[1][2] += a1 * bb.z; acc[1][3] += a1 * bb.w;
            acc[2][0] += a2 * bb.x; acc[2][1] += a2 * bb.y; acc[2][2] += a2 * bb.z; acc[2][3] += a2 * bb.w;
            acc[3][0] += a3 * bb.x; acc[3][1] += a3 * bb.y; acc[3][2] += a3 * bb.z; acc[3][3] += a3 * bb.w;
        }
    }
    #pragma unroll
    for (int i = 0; i < 4; i++) {
        int m = m0 + ty * 4 + i;
        if (m >= cND) continue;
        float* Ar = A + ((size_t)(b * cND + m)) * cD + h * cDH + tx * 4;
        Ar[0] = acc[i][0]; Ar[1] = acc[i][1]; Ar[2] = acc[i][2]; Ar[3] = acc[i][3];
    }
}

// ---------------------------------------------------------------------------
// Launch sequence
// ---------------------------------------------------------------------------
extern "C" void kernel_launch(void* const* d_in, const int* in_sizes, int n_in,
                              void* d_out, int out_size)
{
    (void)in_sizes; (void)n_in; (void)out_size;
    const float* x       = (const float*)d_in[0];
    const float* ctx     = (const float*)d_in[1];
    const float* sos     = (const float*)d_in[2];
    const float* ln1_g   = (const float*)d_in[3];
    const float* ln1_b   = (const float*)d_in[4];
    const float* W_attn  = (const float*)d_in[5];
    const float* b_attn  = (const float*)d_in[6];
    const float* W_ref   = (const float*)d_in[7];
    const float* b_ref   = (const float*)d_in[8];
    const float* W_proj  = (const float*)d_in[9];
    const float* b_proj  = (const float*)d_in[10];
    const float* ln2_g   = (const float*)d_in[11];
    const float* ln2_b   = (const float*)d_in[12];
    const float* W_fc    = (const float*)d_in[13];
    const float* b_fc    = (const float*)d_in[14];
    const float* W_mproj = (const float*)d_in[15];
    const float* b_mproj = (const float*)d_in[16];
    float* out = (float*)d_out;

    float *H, *HL, *QKV, *CKV, *Qb, *Kb, *Vb, *S, *A, *H2, *HL2, *FC;
    cudaGetSymbolAddress((void**)&H,   g_H);
    cudaGetSymbolAddress((void**)&HL,  g_HL);
    cudaGetSymbolAddress((void**)&QKV, g_QKV);
    cudaGetSymbolAddress((void**)&CKV, g_CKV);
    cudaGetSymbolAddress((void**)&Qb,  g_Q);
    cudaGetSymbolAddress((void**)&Kb,  g_K);
    cudaGetSymbolAddress((void**)&Vb,  g_V);
    cudaGetSymbolAddress((void**)&S,   g_S);
    cudaGetSymbolAddress((void**)&A,   g_A);
    cudaGetSymbolAddress((void**)&H2,  g_H2);
    cudaGetSymbolAddress((void**)&HL2, g_HL2);
    cudaGetSymbolAddress((void**)&FC,  g_FC);

    // 1. concat(sos, x) + LN1
    ln_kernel<<<cM, 256>>>(x, sos, ln1_g, ln1_b, H, HL, 1);

    // 2. qkv = ln1(h) @ W_attn + b_attn      [2050 x 2304]
    sgemm_k<128, 128, 8, 8, 8><<<dim3(3 * cD / 128, (cM + 127) / 128), 256>>>(
        HL, W_attn, b_attn, nullptr, QKV, cM, 3 * cD, cD, 0);

    // 3. ckv = context @ W_ref + b_ref       [512 x 1536]
    sgemm_k<64, 64, 16, 4, 4><<<dim3(2 * cD / 64, cMC / 64), 256>>>(
        ctx, W_ref, b_ref, nullptr, CKV, cMC, 2 * cD, cD, 0);

    // 4. per-head gathers
    gather_kv<<<(cBH * cNS * cDH + 255) / 256, 256>>>(QKV, CKV, Kb, Vb);
    gather_q <<<(cBH * cND * cDH + 255) / 256, 256>>>(QKV, Qb);

    // 5. scores + mask, softmax, AV
    attn_scores<<<dim3((cNS + 63) / 64, (cND + 63) / 64, cBH), 256>>>(Qb, Kb, S);
    softmax_rows<<<cBH * cND, 256>>>(S);
    attn_av<<<dim3((cND + 63) / 64, cBH), 256>>>(S, Vb, A);

    // 6. h2 = h + attn @ W_proj + b_proj     [2050 x 768]
    sgemm_k<64, 64, 16, 4, 4><<<dim3(cD / 64, (cM + 63) / 64), 256>>>(
        A, W_proj, b_proj, H, H2, cM, cD, cD, 2);

    // 7. LN2
    ln_kernel<<<cM, 256>>>(H2, nullptr, ln2_g, ln2_b, nullptr, HL2, 0);

    // 8. fc = gelu(ln2(h2) @ W_fc + b_fc)    [2050 x 3072]
    sgemm_k<128, 128, 8, 8, 8><<<dim3(4 * cD / 128, (cM + 127) / 128), 256>>>(
        HL2, W_fc, b_fc, nullptr, FC, cM, 4 * cD, cD, 1);

    // 9. out = (h2 + fc @ W_mproj + b_mproj)[:, 1:, :]   [2050 x 768 -> 2048 rows]
    sgemm_k<64, 64, 16, 4, 4><<<dim3(cD / 64, (cM + 63) / 64), 256>>>(
        FC, W_mproj, b_mproj, H2, out, cM, cD, 4 * cD, 3);
}

// round 7
// speedup vs baseline: 1.0010x; 1.0010x over previous
#include <cuda_runtime.h>
#include <cuda_bf16.h>
#include <math.h>

// ---------------------------------------------------------------------------
// Problem constants (CoconBlock: B=2, S=1024, Sc=256, D=768, H=12, dh=64)
// ---------------------------------------------------------------------------
constexpr int cD   = 768;
constexpr int cH   = 12;
constexpr int cDH  = 64;
constexpr int cB   = 2;
constexpr int cS   = 1024;
constexpr int cSC  = 256;
constexpr int cND  = cS + 1;          // 1025 queries per batch (sos + seq)
constexpr int cNS  = cSC + cND;       // 1281 keys per batch
constexpr int cM   = cB * cND;        // 2050 rows in main activation
constexpr int cMC  = cB * cSC;        // 512 context rows
constexpr int cBH  = cB * cH;         // 24 (batch, head) pairs

// ---------------------------------------------------------------------------
// Scratch (static __device__ arrays; no allocation anywhere)
// ---------------------------------------------------------------------------
__device__ float g_H  [(size_t)cM * cD];          // h  (pre-LN residual stream)
__device__ float g_HL [(size_t)cM * cD];          // ln1(h)
__device__ float g_QKV[(size_t)cM * 3 * cD];      // qkv
__device__ float g_CKV[(size_t)cMC * 2 * cD];     // context k/v
__device__ float g_Q  [(size_t)cBH * cND * cDH];  // per-head Q
__device__ float g_K  [(size_t)cBH * cNS * cDH];  // per-head K (ctx ++ seq)
__device__ float g_V  [(size_t)cBH * cNS * cDH];  // per-head V
__device__ float g_S  [(size_t)cBH * cND * cNS];  // attention scores / probs (126 MB)
__device__ float g_A  [(size_t)cM * cD];          // merged-head attention output
__device__ float g_H2 [(size_t)cM * cD];          // h + attn_proj
__device__ float g_HL2[(size_t)cM * cD];          // ln2(h2)
__device__ float g_FC [(size_t)cM * 4 * cD];      // gelu(fc)

// ---------------------------------------------------------------------------
// Helpers
// ---------------------------------------------------------------------------
__device__ __forceinline__ float gelu_new(float x) {
    float x3 = x * x * x;
    return 0.5f * x * (1.0f + tanhf(0.7978845608028654f * (x + 0.044715f * x3)));
}

// ---------------------------------------------------------------------------
// LayerNorm (optionally fused with the sos-concat gather).
// One block per row, 256 threads, 3 elements/thread (D = 768).
// concat==1: src rows come from {sos | x}, also writes Hout.
// concat==0: src = in + r*768, writes only HLout.
// ---------------------------------------------------------------------------
__global__ __launch_bounds__(256) void ln_kernel(
    const float* __restrict__ in, const float* __restrict__ sos,
    const float* __restrict__ gamma, const float* __restrict__ beta,
    float* __restrict__ Hout, float* __restrict__ HLout, int concat)
{
    int r   = blockIdx.x;
    int tid = threadIdx.x;
    const float* src;
    if (concat) {
        int b = r / cND, t = r % cND;
        src = (t == 0) ? sos : in + ((size_t)b * cS + (t - 1)) * cD;
    } else {
        src = in + (size_t)r * cD;
    }
    float v0 = src[tid], v1 = src[tid + 256], v2 = src[tid + 512];
    float s  = v0 + v1 + v2;
    float ss = v0 * v0 + v1 * v1 + v2 * v2;

    __shared__ float sb[8], sb2[8];
    #pragma unroll
    for (int o = 16; o; o >>= 1) {
        s  += __shfl_xor_sync(0xffffffffu, s,  o);
        ss += __shfl_xor_sync(0xffffffffu, ss, o);
    }
    int lane = tid & 31, w = tid >> 5;
    if (lane == 0) { sb[w] = s; sb2[w] = ss; }
    __syncthreads();
    if (tid == 0) {
        float a = 0.f, c = 0.f;
        #pragma unroll
        for (int i = 0; i < 8; i++) { a += sb[i]; c += sb2[i]; }
        sb[0] = a; sb2[0] = c;
    }
    __syncthreads();
    float mean = sb[0] * (1.0f / 768.0f);
    float var  = sb2[0] * (1.0f / 768.0f) - mean * mean;
    float inv  = rsqrtf(var + 1e-5f);

    if (concat) {
        float* hr = Hout + (size_t)r * cD;
        hr[tid] = v0; hr[tid + 256] = v1; hr[tid + 512] = v2;
    }
    float* hlr = HLout + (size_t)r * cD;
    hlr[tid      ] = (v0 - mean) * inv * gamma[tid      ] + beta[tid      ];
    hlr[tid + 256] = (v1 - mean) * inv * gamma[tid + 256] + beta[tid + 256];
    hlr[tid + 512] = (v2 - mean) * inv * gamma[tid + 512] + beta[tid + 512];
}

// ---------------------------------------------------------------------------
// Generic SGEMM  C[M,N] = A[M,K] @ B[K,N] + bias  (+ epilogue)
// Requires: N % BN == 0, K % BK == 0, BM*BK == BN*BK == 4*THREADS.
// mode: 0 = none, 1 = gelu_new, 2 = + R[r,n], 3 = + R[r,n] then write to
//       out with the sos row dropped (r -> b*1024 + t-1, skip t==0).
// ---------------------------------------------------------------------------
template<int BM, int BN, int BK, int TM, int TN>
__global__ __launch_bounds__((BM / TM) * (BN / TN)) void sgemm_k(
    const float* __restrict__ A, const float* __restrict__ B,
    const float* __restrict__ bias, const float* __restrict__ R,
    float* __restrict__ C, int M, int N, int K, int mode)
{
    constexpr int THREADS = (BM / TM) * (BN / TN);
    static_assert(BM * BK == 4 * THREADS && BN * BK == 4 * THREADS, "load map");
    __shared__ float As[BK][BM];
    __shared__ float Bs[BK][BN];

    const int tid  = threadIdx.x;
    const int row0 = blockIdx.y * BM;
    const int col0 = blockIdx.x * BN;

    const int arow = tid / (BK / 4);
    const int acol = (tid % (BK / 4)) * 4;
    const int brow = tid / (BN / 4);
    const int bcol = (tid % (BN / 4)) * 4;

    constexpr int TX = BN / TN;
    const int tx = tid % TX, ty = tid / TX;

    const bool aval = (row0 + arow) < M;
    const float* Ap = A + (size_t)(row0 + arow) * K + acol;
    const float* Bp = B + (size_t)brow * N + col0 + bcol;

    float acc[TM][TN];
    #pragma unroll
    for (int i = 0; i < TM; i++)
        #pragma unroll
        for (int j = 0; j < TN; j++) acc[i][j] = 0.f;

    for (int kt = 0; kt < K; kt += BK) {
        float4 a4 = aval ? *(const float4*)Ap : make_float4(0.f, 0.f, 0.f, 0.f);
        float4 b4 = *(const float4*)Bp;
        __syncthreads();
        As[acol + 0][arow] = a4.x; As[acol + 1][arow] = a4.y;
        As[acol + 2][arow] = a4.z; As[acol + 3][arow] = a4.w;
        *(float4*)&Bs[brow][bcol] = b4;
        __syncthreads();
        #pragma unroll
        for (int k = 0; k < BK; k++) {
            float ar[TM], br[TN];
            #pragma unroll
            for (int i = 0; i < TM; i += 4)
                *(float4*)&ar[i] = *(const float4*)&As[k][ty * TM + i];
            #pragma unroll
            for (int j = 0; j < TN; j += 4)
                *(float4*)&br[j] = *(const float4*)&Bs[k][tx * TN + j];
            #pragma unroll
            for (int i = 0; i < TM; i++)
                #pragma unroll
                for (int j = 0; j < TN; j++)
                    acc[i][j] += ar[i] * br[j];
        }
        Ap += BK;
        Bp += (size_t)BK * N;
    }

    #pragma unroll
    for (int i = 0; i < TM; i++) {
        int r = row0 + ty * TM + i;
        if (r >= M) continue;
        float* crow;
        if (mode == 3) {
            int bb = r / cND, t = r % cND;
            if (t == 0) continue;                       // drop sos row
            crow = C + ((size_t)(bb * cS + (t - 1))) * N;
        } else {
            crow = C + (size_t)r * N;
        }
        #pragma unroll
        for (int j = 0; j < TN; j++) {
            int c = col0 + tx * TN + j;
            float v = acc[i][j] + bias[c];
            if (mode == 1)      v = gelu_new(v);
            else if (mode >= 2) v += R[(size_t)r * N + c];
            crow[c] = v;
        }
    }
}

// ---------------------------------------------------------------------------
// Head gathers: QKV/CKV -> per-head contiguous Q/K/V buffers
// ---------------------------------------------------------------------------
__global__ void gather_q(const float* __restrict__ QKV, float* __restrict__ Q)
{
    int idx = blockIdx.x * blockDim.x + threadIdx.x;
    if (idx >= cBH * cND * cDH) return;
    int d    = idx & (cDH - 1);
    int rest = idx >> 6;
    int t    = rest % cND;
    int bh   = rest / cND;
    int b = bh / cH, h = bh % cH;
    Q[idx] = QKV[((size_t)(b * cND + t)) * (3 * cD) + h * cDH + d];
}

__global__ void gather_kv(const float* __restrict__ QKV, const float* __restrict__ CKV,
                          float* __restrict__ Kb, float* __restrict__ Vb)
{
    int idx = blockIdx.x * blockDim.x + threadIdx.x;
    if (idx >= cBH * cNS * cDH) return;
    int d    = idx & (cDH - 1);
    int rest = idx >> 6;
    int j    = rest % cNS;
    int bh   = rest / cNS;
    int b = bh / cH, h = bh % cH;
    float kv, vv;
    if (j < cSC) {
        size_t base = ((size_t)(b * cSC + j)) * (2 * cD) + h * cDH + d;
        kv = CKV[base];
        vv = CKV[base + cD];
    } else {
        int t = j - cSC;
        size_t base = ((size_t)(b * cND + t)) * (3 * cD) + h * cDH + d;
        kv = QKV[base + cD];
        vv = QKV[base + 2 * cD];
    }
    Kb[idx] = kv;
    Vb[idx] = vv;
}

// ---------------------------------------------------------------------------
// Scores: S[bh,m,n] = (Q[bh,m,:] . K[bh,n,:]) / 8  if n <= m+Sc else -10000
// Tiles 64x64 over (m,n), full dh=64 in shared memory. Stride-65 smem kills
// the transpose-store bank conflicts.
// ---------------------------------------------------------------------------
__global__ __launch_bounds__(256) void attn_scores(
    const float* __restrict__ Q, const float* __restrict__ Kb, float* __restrict__ S)
{
    __shared__ float Qs[64][65];   // [d][m]
    __shared__ float Ks[64][65];   // [d][n]
    int bh = blockIdx.z;
    int m0 = blockIdx.y * 64;
    int n0 = blockIdx.x * 64;
    int tid = threadIdx.x;
    int lr = tid >> 4;
    int lc = (tid & 15) * 4;
    const float* Qb  = Q  + ((size_t)bh * cND + m0) * cDH;
    const float* Kbb = Kb + ((size_t)bh * cNS + n0) * cDH;

    #pragma unroll
    for (int it = 0; it < 4; it++) {
        int m = lr + it * 16;
        float4 v = make_float4(0.f, 0.f, 0.f, 0.f);
        if (m0 + m < cND) v = *(const float4*)(Qb + (size_t)m * cDH + lc);
        Qs[lc + 0][m] = v.x; Qs[lc + 1][m] = v.y;
        Qs[lc + 2][m] = v.z; Qs[lc + 3][m] = v.w;
        float4 w = make_float4(0.f, 0.f, 0.f, 0.f);
        if (n0 + m < cNS) w = *(const float4*)(Kbb + (size_t)m * cDH + lc);
        Ks[lc + 0][m] = w.x; Ks[lc + 1][m] = w.y;
        Ks[lc + 2][m] = w.z; Ks[lc + 3][m] = w.w;
    }
    __syncthreads();

    int tx = tid & 15, ty = tid >> 4;
    float acc[4][4] = {};
    #pragma unroll 8
    for (int k = 0; k < 64; k++) {
        float a0 = Qs[k][ty * 4 + 0], a1 = Qs[k][ty * 4 + 1];
        float a2 = Qs[k][ty * 4 + 2], a3 = Qs[k][ty * 4 + 3];
        float b0 = Ks[k][tx * 4 + 0], b1 = Ks[k][tx * 4 + 1];
        float b2 = Ks[k][tx * 4 + 2], b3 = Ks[k][tx * 4 + 3];
        acc[0][0] += a0 * b0; acc[0][1] += a0 * b1; acc[0][2] += a0 * b2; acc[0][3] += a0 * b3;
        acc[1][0] += a1 * b0; acc[1][1] += a1 * b1; acc[1][2] += a1 * b2; acc[1][3] += a1 * b3;
        acc[2][0] += a2 * b0; acc[2][1] += a2 * b1; acc[2][2] += a2 * b2; acc[2][3] += a2 * b3;
        acc[3][0] += a3 * b0; acc[3][1] += a3 * b1; acc[3][2] += a3 * b2; acc[3][3] += a3 * b3;
    }

    const float scale = 0.125f;   // 1/sqrt(64)
    #pragma unroll
    for (int i = 0; i < 4; i++) {
        int m = m0 + ty * 4 + i;
        if (m >= cND) continue;
        float* Sr = S + ((size_t)bh * cND + m) * cNS;
        #pragma unroll
        for (int j = 0; j < 4; j++) {
            int n = n0 + tx * 4 + j;
            if (n >= cNS) continue;
            Sr[n] = (n <= m + cSC) ? acc[i][j] * scale : -10000.0f;
        }
    }
}

// ---------------------------------------------------------------------------
// Row softmax over ns=1281, one block per (bh, query) row; values stay in
// registers across the three phases (max, exp+sum, normalize).
// ---------------------------------------------------------------------------
__global__ __launch_bounds__(256) void softmax_rows(float* __restrict__ S)
{
    size_t row = blockIdx.x;
    float* p = S + row * (size_t)cNS;
    int tid = threadIdx.x;
    float vals[6];
    float mx = -3.4e38f;
    #pragma unroll
    for (int it = 0; it < 6; it++) {
        int i = tid + it * 256;
        float v = (i < cNS) ? p[i] : -3.4e38f;
        vals[it] = v;
        mx = fmaxf(mx, v);
    }
    __shared__ float sb[8];
    #pragma unroll
    for (int o = 16; o; o >>= 1) mx = fmaxf(mx, __shfl_xor_sync(0xffffffffu, mx, o));
    if ((tid & 31) == 0) sb[tid >> 5] = mx;
    __syncthreads();
    if (tid < 32) {
        float m2 = (tid < 8) ? sb[tid] : -3.4e38f;
        #pragma unroll
        for (int o = 4; o; o >>= 1) m2 = fmaxf(m2, __shfl_xor_sync(0xffffffffu, m2, o));
        if (tid == 0) sb[0] = m2;
    }
    __syncthreads();
    float bmax = sb[0];
    __syncthreads();

    float s = 0.f;
    #pragma unroll
    for (int it = 0; it < 6; it++) {
        int i = tid + it * 256;
        if (i < cNS) {
            float e = __expf(vals[it] - bmax);
            vals[it] = e;
            s += e;
        }
    }
    #pragma unroll
    for (int o = 16; o; o >>= 1) s += __shfl_xor_sync(0xffffffffu, s, o);
    if ((tid & 31) == 0) sb[tid >> 5] = s;
    __syncthreads();
    if (tid < 32) {
        float s2 = (tid < 8) ? sb[tid] : 0.f;
        #pragma unroll
        for (int o = 4; o; o >>= 1) s2 += __shfl_xor_sync(0xffffffffu, s2, o);
        if (tid == 0) sb[0] = s2;
    }
    __syncthreads();
    float inv = 1.0f / sb[0];
    #pragma unroll
    for (int it = 0; it < 6; it++) {
        int i = tid + it * 256;
        if (i < cNS) p[i] = vals[it] * inv;
    }
}

// ---------------------------------------------------------------------------
// AV: O[bh,m,d] = sum_j P[bh,m,j] * V[bh,j,d]; writes directly into the
// merged-head layout A[(b*nd+m), h*64+d] so no extra transpose is needed.
// ---------------------------------------------------------------------------
__global__ __launch_bounds__(256) void attn_av(
    const float* __restrict__ P, const float* __restrict__ Vb, float* __restrict__ A)
{
    __shared__ float Ps[16][65];   // [k][m]
    __shared__ float Vs[16][64];   // [k][d]
    int bh = blockIdx.y;
    int b = bh / cH, h = bh % cH;
    int m0 = blockIdx.x * 64;
    int tid = threadIdx.x;
    int pr = tid >> 2, pc = (tid & 3) * 4;
    int vr = tid >> 4, vc = (tid & 15) * 4;
    int tx = tid & 15, ty = tid >> 4;

    const float* Pb  = P  + ((size_t)bh * cND + m0) * cNS;
    const float* Vbb = Vb + (size_t)bh * cNS * cDH;
    const bool pval = (m0 + pr) < cND;

    float acc[4][4] = {};
    for (int kt = 0; kt < cNS; kt += 16) {
        float p0 = 0.f, p1 = 0.f, p2 = 0.f, p3 = 0.f;
        if (pval) {
            const float* pp = Pb + (size_t)pr * cNS;   // rows are odd-length: scalar loads
            int kk = kt + pc;
            if (kk + 3 < cNS) { p0 = pp[kk]; p1 = pp[kk + 1]; p2 = pp[kk + 2]; p3 = pp[kk + 3]; }
            else {
                if (kk     < cNS) p0 = pp[kk];
                if (kk + 1 < cNS) p1 = pp[kk + 1];
                if (kk + 2 < cNS) p2 = pp[kk + 2];
            }
        }
        float4 vv = make_float4(0.f, 0.f, 0.f, 0.f);
        if (kt + vr < cNS) vv = *(const float4*)(Vbb + (size_t)(kt + vr) * cDH + vc);
        __syncthreads();
        Ps[pc + 0][pr] = p0; Ps[pc + 1][pr] = p1;
        Ps[pc + 2][pr] = p2; Ps[pc + 3][pr] = p3;
        *(float4*)&Vs[vr][vc] = vv;
        __syncthreads();
        #pragma unroll
        for (int k = 0; k < 16; k++) {
            float a0 = Ps[k][ty * 4 + 0], a1 = Ps[k][ty * 4 + 1];
            float a2 = Ps[k][ty * 4 + 2], a3 = Ps[k][ty * 4 + 3];
            float4 bb = *(const float4*)&Vs[k][tx * 4];
            acc[0][0] += a0 * bb.x; acc[0][1] += a0 * bb.y; acc[0][2] += a0 * bb.z; acc[0][3] += a0 * bb.w;
            acc[1][0] += a1 * bb.x; acc[1][1] += a1 * bb.y; acc[1][2] += a1 * bb.z; acc[1][3] += a1 * bb.w;
            acc[2][0] += a2 * bb.x; acc[2][1] += a2 * bb.y; acc[2][2] += a2 * bb.z; acc[2][3] += a2 * bb.w;
            acc[3][0] += a3 * bb.x; acc[3][1] += a3 * bb.y; acc[3][2] += a3 * bb.z; acc[3][3] += a3 * bb.w;
        }
    }
    #pragma unroll
    for (int i = 0; i < 4; i++) {
        int m = m0 + ty * 4 + i;
        if (m >= cND) continue;
        float* Ar = A + ((size_t)(b * cND + m)) * cD + h * cDH + tx * 4;
        Ar[0] = acc[i][0]; Ar[1] = acc[i][1]; Ar[2] = acc[i][2]; Ar[3] = acc[i][3];
    }
}

// ---------------------------------------------------------------------------
// Launch sequence
// ---------------------------------------------------------------------------
extern "C" void kernel_launch(void* const* d_in, const int* in_sizes, int n_in,
                              void* d_out, int out_size)
{
    (void)in_sizes; (void)n_in; (void)out_size;
    const float* x       = (const float*)d_in[0];
    const float* ctx     = (const float*)d_in[1];
    const float* sos     = (const float*)d_in[2];
    const float* ln1_g   = (const float*)d_in[3];
    const float* ln1_b   = (const float*)d_in[4];
    const float* W_attn  = (const float*)d_in[5];
    const float* b_attn  = (const float*)d_in[6];
    const float* W_ref   = (const float*)d_in[7];
    const float* b_ref   = (const float*)d_in[8];
    const float* W_proj  = (const float*)d_in[9];
    const float* b_proj  = (const float*)d_in[10];
    const float* ln2_g   = (const float*)d_in[11];
    const float* ln2_b   = (const float*)d_in[12];
    const float* W_fc    = (const float*)d_in[13];
    const float* b_fc    = (const float*)d_in[14];
    const float* W_mproj = (const float*)d_in[15];
    const float* b_mproj = (const float*)d_in[16];
    float* out = (float*)d_out;

    float *H, *HL, *QKV, *CKV, *Qb, *Kb, *Vb, *S, *A, *H2, *HL2, *FC;
    cudaGetSymbolAddress((void**)&H,   g_H);
    cudaGetSymbolAddress((void**)&HL,  g_HL);
    cudaGetSymbolAddress((void**)&QKV, g_QKV);
    cudaGetSymbolAddress((void**)&CKV, g_CKV);
    cudaGetSymbolAddress((void**)&Qb,  g_Q);
    cudaGetSymbolAddress((void**)&Kb,  g_K);
    cudaGetSymbolAddress((void**)&Vb,  g_V);
    cudaGetSymbolAddress((void**)&S,   g_S);
    cudaGetSymbolAddress((void**)&A,   g_A);
    cudaGetSymbolAddress((void**)&H2,  g_H2);
    cudaGetSymbolAddress((void**)&HL2, g_HL2);
    cudaGetSymbolAddress((void**)&FC,  g_FC);

    // 1. concat(sos, x) + LN1
    ln_kernel<<<cM, 256>>>(x, sos, ln1_g, ln1_b, H, HL, 1);

    // 2. qkv = ln1(h) @ W_attn + b_attn      [2050 x 2304]
    sgemm_k<128, 128, 8, 8, 8><<<dim3(3 * cD / 128, (cM + 127) / 128), 256>>>(
        HL, W_attn, b_attn, nullptr, QKV, cM, 3 * cD, cD, 0);

    // 3. ckv = context @ W_ref + b_ref       [512 x 1536]
    sgemm_k<64, 64, 16, 4, 4><<<dim3(2 * cD / 64, cMC / 64), 256>>>(
        ctx, W_ref, b_ref, nullptr, CKV, cMC, 2 * cD, cD, 0);

    // 4. per-head gathers
    gather_kv<<<(cBH * cNS * cDH + 255) / 256, 256>>>(QKV, CKV, Kb, Vb);
    gather_q <<<(cBH * cND * cDH + 255) / 256, 256>>>(QKV, Qb);

    // 5. scores + mask, softmax, AV
    attn_scores<<<dim3((cNS + 63) / 64, (cND + 63) / 64, cBH), 256>>>(Qb, Kb, S);
    softmax_rows<<<cBH * cND, 256>>>(S);
    attn_av<<<dim3((cND + 63) / 64, cBH), 256>>>(S, Vb, A);

    // 6. h2 = h + attn @ W_proj + b_proj     [2050 x 768]
    sgemm_k<64, 64, 16, 4, 4><<<dim3(cD / 64, (cM + 63) / 64), 256>>>(
        A, W_proj, b_proj, H, H2, cM, cD, cD, 2);

    // 7. LN2
    ln_kernel<<<cM, 256>>>(H2, nullptr, ln2_g, ln2_b, nullptr, HL2, 0);

    // 8. fc = gelu(ln2(h2) @ W_fc + b_fc)    [2050 x 3072]
    sgemm_k<128, 128, 8, 8, 8><<<dim3(4 * cD / 128, (cM + 127) / 128), 256>>>(
        HL2, W_fc, b_fc, nullptr, FC, cM, 4 * cD, cD, 1);

    // 9. out = (h2 + fc @ W_mproj + b_mproj)[:, 1:, :]   [2050 x 768 -> 2048 rows]
    sgemm_k<64, 64, 16, 4, 4><<<dim3(cD / 64, (cM + 63) / 64), 256>>>(
        FC, W_mproj, b_mproj, H2, out, cM, cD, 4 * cD, 3);
}

// round 9
// speedup vs baseline: 1.6337x; 1.6320x over previous
#include <cuda_runtime.h>
#include <cuda_bf16.h>
#include <math.h>
#include <stdint.h>

// ---------------------------------------------------------------------------
// Problem constants (CoconBlock: B=2, S=1024, Sc=256, D=768, H=12, dh=64)
// ---------------------------------------------------------------------------
constexpr int cD   = 768;
constexpr int cH   = 12;
constexpr int cDH  = 64;
constexpr int cB   = 2;
constexpr int cS   = 1024;
constexpr int cSC  = 256;
constexpr int cND  = cS + 1;          // 1025 queries per batch (sos + seq)
constexpr int cNS  = cSC + cND;       // 1281 keys per batch
constexpr int cM   = cB * cND;        // 2050 rows in main activation
constexpr int cMC  = cB * cSC;        // 512 context rows
constexpr int cBH  = cB * cH;         // 24 (batch, head) pairs
constexpr int cMPAD = 2176;           // 17 * 128 (padded row count for MMA tiles)

// ---------------------------------------------------------------------------
// Scratch (static __device__ arrays; no allocation anywhere)
// ---------------------------------------------------------------------------
__device__ float g_H  [(size_t)cM * cD];
__device__ float g_HL [(size_t)cM * cD];
__device__ float g_QKV[(size_t)cM * 3 * cD];
__device__ float g_CKV[(size_t)cMC * 2 * cD];
__device__ float g_Q  [(size_t)cBH * cND * cDH];
__device__ float g_K  [(size_t)cBH * cNS * cDH];
__device__ float g_V  [(size_t)cBH * cNS * cDH];
__device__ float g_S  [(size_t)cBH * cND * cNS];
__device__ float g_A  [(size_t)cM * cD];
__device__ float g_H2 [(size_t)cM * cD];
__device__ float g_HL2[(size_t)cM * cD];
__device__ float g_FC [(size_t)cM * 4 * cD];
// bf16 split operands (reused per GEMM, sequential)
__device__ __nv_bfloat16 g_As[(size_t)cMPAD * 3 * 3072];    // A' [Mpad, 3K], K<=3072
__device__ __nv_bfloat16 g_Bs[(size_t)3072 * 2304];          // B' [N, 3K], max 3072x2304

// ---------------------------------------------------------------------------
// Small helpers
// ---------------------------------------------------------------------------
__device__ __forceinline__ float gelu_new(float x) {
    float x3 = x * x * x;
    return 0.5f * x * (1.0f + tanhf(0.7978845608028654f * (x + 0.044715f * x3)));
}
__device__ __forceinline__ uint32_t smem_u32(const void* p) {
    uint32_t a;
    asm("{ .reg .u64 t; cvta.to.shared.u64 t, %1; cvt.u32.u64 %0, t; }" : "=r"(a) : "l"(p));
    return a;
}
__device__ __forceinline__ void cp16(uint32_t s, const void* g) {
    asm volatile("cp.async.cg.shared.global [%0], [%1], 16;\n"
                 :: "r"(s), "l"(__cvta_generic_to_global(g)) : "memory");
}
__device__ __forceinline__ void ldsm_x4(uint32_t& r0, uint32_t& r1, uint32_t& r2,
                                        uint32_t& r3, uint32_t addr) {
    asm volatile("ldmatrix.sync.aligned.m8n8.x4.shared.b16 {%0,%1,%2,%3}, [%4];"
                 : "=r"(r0), "=r"(r1), "=r"(r2), "=r"(r3) : "r"(addr));
}
__device__ __forceinline__ void ldsm_x2(uint32_t& r0, uint32_t& r1, uint32_t addr) {
    asm volatile("ldmatrix.sync.aligned.m8n8.x2.shared.b16 {%0,%1}, [%2];"
                 : "=r"(r0), "=r"(r1) : "r"(addr));
}
__device__ __forceinline__ void mma16816(float* c, const uint32_t* a, const uint32_t* b) {
    asm volatile(
        "mma.sync.aligned.m16n8k16.row.col.f32.bf16.bf16.f32 "
        "{%0,%1,%2,%3}, {%4,%5,%6,%7}, {%8,%9}, {%0,%1,%2,%3};"
        : "+f"(c[0]), "+f"(c[1]), "+f"(c[2]), "+f"(c[3])
        : "r"(a[0]), "r"(a[1]), "r"(a[2]), "r"(a[3]), "r"(b[0]), "r"(b[1]));
}

// ---------------------------------------------------------------------------
// Split conversion kernels
//   A' per original k: [hi_a, lo_a, hi_a];  B' per k: [hi_b, hi_b, lo_b]
//   sum over 3 slots = hi*hi + lo*hi + hi*lo ~= a*b  (error ~2^-17)
// ---------------------------------------------------------------------------
__global__ __launch_bounds__(256) void act_split(
    const float* __restrict__ X, __nv_bfloat16* __restrict__ Y, int MK, int K)
{
    int idx = blockIdx.x * 256 + threadIdx.x;
    if (idx >= MK) return;
    int m = idx / K, k = idx % K;
    float x = X[idx];
    __nv_bfloat16 hi = __float2bfloat16(x);
    __nv_bfloat16 lo = __float2bfloat16(x - __bfloat162float(hi));
    size_t o = (size_t)m * (3 * K) + 3 * k;
    Y[o] = hi; Y[o + 1] = lo; Y[o + 2] = hi;
}

// W [K,N] fp32 -> Y [N, 3K] bf16 ([hi,hi,lo] per k), smem tile transpose
__global__ __launch_bounds__(256) void w_split(
    const float* __restrict__ W, __nv_bfloat16* __restrict__ Y, int K, int N)
{
    __shared__ float t[32][33];
    int k0 = blockIdx.y * 32, n0 = blockIdx.x * 32;
    int tid = threadIdx.x;
    #pragma unroll
    for (int p = 0; p < 4; p++) {
        int idx = p * 256 + tid;
        int kk = idx >> 5, nn = idx & 31;
        t[kk][nn] = W[(size_t)(k0 + kk) * N + n0 + nn];
    }
    __syncthreads();
    #pragma unroll
    for (int p = 0; p < 4; p++) {
        int idx = p * 256 + tid;
        int nn = idx >> 5, kk = idx & 31;
        float x = t[kk][nn];
        __nv_bfloat16 hi = __float2bfloat16(x);
        __nv_bfloat16 lo = __float2bfloat16(x - __bfloat162float(hi));
        size_t o = (size_t)(n0 + nn) * (3 * (size_t)K) + 3 * (size_t)(k0 + kk);
        Y[o] = hi; Y[o + 1] = hi; Y[o + 2] = lo;
    }
}

// ---------------------------------------------------------------------------
// HMMA (mma.sync bf16) GEMM: C[M,N] = A'[M,K3] x B'[N,K3]^T (+bias, +epilogue)
// 128x128 tile per CTA, 256 threads (8 warps, 2x4; 64x32 per warp),
// BK=64, double-buffered cp.async, 144B row pitch (conflict-free ldmatrix).
// mode: 0 none, 1 gelu_new, 2 +R, 3 +R then write with sos row dropped.
// ---------------------------------------------------------------------------
constexpr int TG_PITCH = 144;                 // 64 bf16 = 128B + 16B pad
constexpr int TG_STG   = 128 * TG_PITCH;      // one A or B stage = 18432B
constexpr int TG_SMEM  = 4 * TG_STG + 128;    // A0,A1,B0,B1 + align pad

__global__ __launch_bounds__(256, 2) void tgemm(
    const __nv_bfloat16* __restrict__ A3, const __nv_bfloat16* __restrict__ B3,
    const float* __restrict__ bias, const float* __restrict__ R,
    float* __restrict__ C, int M, int N, int K3, int mode)
{
    extern __shared__ char dynraw[];
    char* sb = (char*)(((uintptr_t)dynraw + 127) & ~(uintptr_t)127);
    const uint32_t sA0 = smem_u32(sb);
    const uint32_t sB0 = sA0 + 2 * TG_STG;

    const int tid  = threadIdx.x;
    const int wid  = tid >> 5;
    const int lane = tid & 31;
    const int g    = lane >> 2;         // quad group id
    const int tg   = lane & 3;          // thread in group
    const int wm   = wid >> 2;          // 0..1
    const int wn   = wid & 3;           // 0..3
    const int row0 = blockIdx.y * 128;
    const int col0 = blockIdx.x * 128;

    // cp.async maps: 4 x 16B per operand per thread per BK=64 chunk
    uint32_t soff[4];
    const __nv_bfloat16 *Ag[4], *Bg[4];
    #pragma unroll
    for (int p = 0; p < 4; p++) {
        int idx = p * 256 + tid;          // 0..1023
        int row = idx >> 3, seg = idx & 7;
        soff[p] = (uint32_t)(row * TG_PITCH + seg * 16);
        Ag[p] = A3 + (size_t)(row0 + row) * K3 + seg * 8;
        Bg[p] = B3 + (size_t)(col0 + row) * K3 + seg * 8;
    }

    // ldmatrix per-lane base offsets
    const uint32_t aoff = (uint32_t)((wm * 64 + (lane & 15)) * TG_PITCH + (lane >> 4) * 16);
    const uint32_t boff = (uint32_t)((wn * 32 + (lane & 7)) * TG_PITCH + ((lane >> 3) & 1) * 16);

    float c[4][4][4];
    #pragma unroll
    for (int mi = 0; mi < 4; mi++)
        #pragma unroll
        for (int ni = 0; ni < 4; ni++)
            #pragma unroll
            for (int e = 0; e < 4; e++) c[mi][ni][e] = 0.f;

    const int nch = K3 >> 6;

    // Prologue: chunk 0 -> stage 0
    #pragma unroll
    for (int p = 0; p < 4; p++) {
        cp16(sA0 + soff[p], Ag[p]);
        cp16(sB0 + soff[p], Bg[p]);
    }
    asm volatile("cp.async.commit_group;" ::: "memory");

    for (int i = 0; i < nch; i++) {
        const int st = i & 1;
        if (i + 1 < nch) {
            const int st2 = (i + 1) & 1;
            const int ko = (i + 1) * 64;
            #pragma unroll
            for (int p = 0; p < 4; p++) {
                cp16(sA0 + st2 * TG_STG + soff[p], Ag[p] + ko);
                cp16(sB0 + st2 * TG_STG + soff[p], Bg[p] + ko);
            }
            asm volatile("cp.async.commit_group;" ::: "memory");
            asm volatile("cp.async.wait_group 1;" ::: "memory");
        } else {
            asm volatile("cp.async.wait_group 0;" ::: "memory");
        }
        __syncthreads();

        const uint32_t sa = sA0 + st * TG_STG + aoff;
        const uint32_t sbb = sB0 + st * TG_STG + boff;
        #pragma unroll
        for (int ks = 0; ks < 4; ks++) {
            uint32_t a[4][4], b[4][2];
            #pragma unroll
            for (int mi = 0; mi < 4; mi++)
                ldsm_x4(a[mi][0], a[mi][1], a[mi][2], a[mi][3],
                        sa + (uint32_t)(mi * 16 * TG_PITCH + ks * 32));
            #pragma unroll
            for (int ni = 0; ni < 4; ni++)
                ldsm_x2(b[ni][0], b[ni][1],
                        sbb + (uint32_t)(ni * 8 * TG_PITCH + ks * 32));
            #pragma unroll
            for (int mi = 0; mi < 4; mi++)
                #pragma unroll
                for (int ni = 0; ni < 4; ni++)
                    mma16816(c[mi][ni], a[mi], b[ni]);
        }
        __syncthreads();
    }

    // Epilogue: D fragment c0/c1 = (row g, cols 2t,2t+1), c2/c3 = row g+8.
    #pragma unroll
    for (int mi = 0; mi < 4; mi++) {
        #pragma unroll
        for (int half = 0; half < 2; half++) {
            int rg = row0 + wm * 64 + mi * 16 + g + half * 8;
            if (rg >= M) continue;
            float* crow;
            if (mode == 3) {
                int t = rg % cND;
                if (t == 0) continue;
                crow = C + ((size_t)((rg / cND) * cS + (t - 1))) * N;
            } else {
                crow = C + (size_t)rg * N;
            }
            #pragma unroll
            for (int ni = 0; ni < 4; ni++) {
                int cg = col0 + wn * 32 + ni * 8 + 2 * tg;
                float v0 = c[mi][ni][half * 2 + 0] + __ldg(&bias[cg]);
                float v1 = c[mi][ni][half * 2 + 1] + __ldg(&bias[cg + 1]);
                if (mode == 1) { v0 = gelu_new(v0); v1 = gelu_new(v1); }
                else if (mode >= 2) {
                    v0 += R[(size_t)rg * N + cg];
                    v1 += R[(size_t)rg * N + cg + 1];
                }
                *(float2*)(crow + cg) = make_float2(v0, v1);
            }
        }
    }
}

// ---------------------------------------------------------------------------
// LayerNorm (optionally fused with sos-concat gather)
// ---------------------------------------------------------------------------
__global__ __launch_bounds__(256) void ln_kernel(
    const float* __restrict__ in, const float* __restrict__ sos,
    const float* __restrict__ gamma, const float* __restrict__ beta,
    float* __restrict__ Hout, float* __restrict__ HLout, int concat)
{
    int r   = blockIdx.x;
    int tid = threadIdx.x;
    const float* src;
    if (concat) {
        int b = r / cND, t = r % cND;
        src = (t == 0) ? sos : in + ((size_t)b * cS + (t - 1)) * cD;
    } else {
        src = in + (size_t)r * cD;
    }
    float v0 = src[tid], v1 = src[tid + 256], v2 = src[tid + 512];
    float s  = v0 + v1 + v2;
    float ss = v0 * v0 + v1 * v1 + v2 * v2;

    __shared__ float sb[8], sb2[8];
    #pragma unroll
    for (int o = 16; o; o >>= 1) {
        s  += __shfl_xor_sync(0xffffffffu, s,  o);
        ss += __shfl_xor_sync(0xffffffffu, ss, o);
    }
    int lane = tid & 31, w = tid >> 5;
    if (lane == 0) { sb[w] = s; sb2[w] = ss; }
    __syncthreads();
    if (tid == 0) {
        float a = 0.f, c = 0.f;
        #pragma unroll
        for (int i = 0; i < 8; i++) { a += sb[i]; c += sb2[i]; }
        sb[0] = a; sb2[0] = c;
    }
    __syncthreads();
    float mean = sb[0] * (1.0f / 768.0f);
    float var  = sb2[0] * (1.0f / 768.0f) - mean * mean;
    float inv  = rsqrtf(var + 1e-5f);

    if (concat) {
        float* hr = Hout + (size_t)r * cD;
        hr[tid] = v0; hr[tid + 256] = v1; hr[tid + 512] = v2;
    }
    float* hlr = HLout + (size_t)r * cD;
    hlr[tid      ] = (v0 - mean) * inv * gamma[tid      ] + beta[tid      ];
    hlr[tid + 256] = (v1 - mean) * inv * gamma[tid + 256] + beta[tid + 256];
    hlr[tid + 512] = (v2 - mean) * inv * gamma[tid + 512] + beta[tid + 512];
}

// ---------------------------------------------------------------------------
// Head gathers
// ---------------------------------------------------------------------------
__global__ void gather_q(const float* __restrict__ QKV, float* __restrict__ Q)
{
    int idx = blockIdx.x * blockDim.x + threadIdx.x;
    if (idx >= cBH * cND * cDH) return;
    int d    = idx & (cDH - 1);
    int rest = idx >> 6;
    int t    = rest % cND;
    int bh   = rest / cND;
    int b = bh / cH, h = bh % cH;
    Q[idx] = QKV[((size_t)(b * cND + t)) * (3 * cD) + h * cDH + d];
}

__global__ void gather_kv(const float* __restrict__ QKV, const float* __restrict__ CKV,
                          float* __restrict__ Kb, float* __restrict__ Vb)
{
    int idx = blockIdx.x * blockDim.x + threadIdx.x;
    if (idx >= cBH * cNS * cDH) return;
    int d    = idx & (cDH - 1);
    int rest = idx >> 6;
    int j    = rest % cNS;
    int bh   = rest / cNS;
    int b = bh / cH, h = bh % cH;
    float kv, vv;
    if (j < cSC) {
        size_t base = ((size_t)(b * cSC + j)) * (2 * cD) + h * cDH + d;
        kv = CKV[base];
        vv = CKV[base + cD];
    } else {
        int t = j - cSC;
        size_t base = ((size_t)(b * cND + t)) * (3 * cD) + h * cDH + d;
        kv = QKV[base + cD];
        vv = QKV[base + 2 * cD];
    }
    Kb[idx] = kv;
    Vb[idx] = vv;
}

// ---------------------------------------------------------------------------
// Attention scores (FFMA), softmax, AV
// ---------------------------------------------------------------------------
__global__ __launch_bounds__(256) void attn_scores(
    const float* __restrict__ Q, const float* __restrict__ Kb, float* __restrict__ S)
{
    __shared__ float Qs[64][65];
    __shared__ float Ks[64][65];
    int bh = blockIdx.z;
    int m0 = blockIdx.y * 64;
    int n0 = blockIdx.x * 64;
    int tid = threadIdx.x;
    int lr = tid >> 4;
    int lc = (tid & 15) * 4;
    const float* Qb  = Q  + ((size_t)bh * cND + m0) * cDH;
    const float* Kbb = Kb + ((size_t)bh * cNS + n0) * cDH;

    #pragma unroll
    for (int it = 0; it < 4; it++) {
        int m = lr + it * 16;
        float4 v = make_float4(0.f, 0.f, 0.f, 0.f);
        if (m0 + m < cND) v = *(const float4*)(Qb + (size_t)m * cDH + lc);
        Qs[lc + 0][m] = v.x; Qs[lc + 1][m] = v.y;
        Qs[lc + 2][m] = v.z; Qs[lc + 3][m] = v.w;
        float4 w = make_float4(0.f, 0.f, 0.f, 0.f);
        if (n0 + m < cNS) w = *(const float4*)(Kbb + (size_t)m * cDH + lc);
        Ks[lc + 0][m] = w.x; Ks[lc + 1][m] = w.y;
        Ks[lc + 2][m] = w.z; Ks[lc + 3][m] = w.w;
    }
    __syncthreads();

    int tx = tid & 15, ty = tid >> 4;
    float acc[4][4] = {};
    #pragma unroll 8
    for (int k = 0; k < 64; k++) {
        float a0 = Qs[k][ty * 4 + 0], a1 = Qs[k][ty * 4 + 1];
        float a2 = Qs[k][ty * 4 + 2], a3 = Qs[k][ty * 4 + 3];
        float b0 = Ks[k][tx * 4 + 0], b1 = Ks[k][tx * 4 + 1];
        float b2 = Ks[k][tx * 4 + 2], b3 = Ks[k][tx * 4 + 3];
        acc[0][0] += a0 * b0; acc[0][1] += a0 * b1; acc[0][2] += a0 * b2; acc[0][3] += a0 * b3;
        acc[1][0] += a1 * b0; acc[1][1] += a1 * b1; acc[1][2] += a1 * b2; acc[1][3] += a1 * b3;
        acc[2][0] += a2 * b0; acc[2][1] += a2 * b1; acc[2][2] += a2 * b2; acc[2][3] += a2 * b3;
        acc[3][0] += a3 * b0; acc[3][1] += a3 * b1; acc[3][2] += a3 * b2; acc[3][3] += a3 * b3;
    }

    const float scale = 0.125f;
    #pragma unroll
    for (int i = 0; i < 4; i++) {
        int m = m0 + ty * 4 + i;
        if (m >= cND) continue;
        float* Sr = S + ((size_t)bh * cND + m) * cNS;
        #pragma unroll
        for (int j = 0; j < 4; j++) {
            int n = n0 + tx * 4 + j;
            if (n >= cNS) continue;
            Sr[n] = (n <= m + cSC) ? acc[i][j] * scale : -10000.0f;
        }
    }
}

__global__ __launch_bounds__(256) void softmax_rows(float* __restrict__ S)
{
    size_t row = blockIdx.x;
    float* p = S + row * (size_t)cNS;
    int tid = threadIdx.x;
    float vals[6];
    float mx = -3.4e38f;
    #pragma unroll
    for (int it = 0; it < 6; it++) {
        int i = tid + it * 256;
        float v = (i < cNS) ? p[i] : -3.4e38f;
        vals[it] = v;
        mx = fmaxf(mx, v);
    }
    __shared__ float sb[8];
    #pragma unroll
    for (int o = 16; o; o >>= 1) mx = fmaxf(mx, __shfl_xor_sync(0xffffffffu, mx, o));
    if ((tid & 31) == 0) sb[tid >> 5] = mx;
    __syncthreads();
    if (tid < 32) {
        float m2 = (tid < 8) ? sb[tid] : -3.4e38f;
        #pragma unroll
        for (int o = 4; o; o >>= 1) m2 = fmaxf(m2, __shfl_xor_sync(0xffffffffu, m2, o));
        if (tid == 0) sb[0] = m2;
    }
    __syncthreads();
    float bmax = sb[0];
    __syncthreads();

    float s = 0.f;
    #pragma unroll
    for (int it = 0; it < 6; it++) {
        int i = tid + it * 256;
        if (i < cNS) {
            float e = __expf(vals[it] - bmax);
            vals[it] = e;
            s += e;
        }
    }
    #pragma unroll
    for (int o = 16; o; o >>= 1) s += __shfl_xor_sync(0xffffffffu, s, o);
    if ((tid & 31) == 0) sb[tid >> 5] = s;
    __syncthreads();
    if (tid < 32) {
        float s2 = (tid < 8) ? sb[tid] : 0.f;
        #pragma unroll
        for (int o = 4; o; o >>= 1) s2 += __shfl_xor_sync(0xffffffffu, s2, o);
        if (tid == 0) sb[0] = s2;
    }
    __syncthreads();
    float inv = 1.0f / sb[0];
    #pragma unroll
    for (int it = 0; it < 6; it++) {
        int i = tid + it * 256;
        if (i < cNS) p[i] = vals[it] * inv;
    }
}

__global__ __launch_bounds__(256) void attn_av(
    const float* __restrict__ P, const float* __restrict__ Vb, float* __restrict__ A)
{
    __shared__ float Ps[16][65];
    __shared__ float Vs[16][64];
    int bh = blockIdx.y;
    int b = bh / cH, h = bh % cH;
    int m0 = blockIdx.x * 64;
    int tid = threadIdx.x;
    int pr = tid >> 2, pc = (tid & 3) * 4;
    int vr = tid >> 4, vc = (tid & 15) * 4;
    int tx = tid & 15, ty = tid >> 4;

    const float* Pb  = P  + ((size_t)bh * cND + m0) * cNS;
    const float* Vbb = Vb + (size_t)bh * cNS * cDH;
    const bool pval = (m0 + pr) < cND;

    float acc[4][4] = {};
    for (int kt = 0; kt < cNS; kt += 16) {
        float p0 = 0.f, p1 = 0.f, p2 = 0.f, p3 = 0.f;
        if (pval) {
            const float* pp = Pb + (size_t)pr * cNS;
            int kk = kt + pc;
            if (kk + 3 < cNS) { p0 = pp[kk]; p1 = pp[kk + 1]; p2 = pp[kk + 2]; p3 = pp[kk + 3]; }
            else {
                if (kk     < cNS) p0 = pp[kk];
                if (kk + 1 < cNS) p1 = pp[kk + 1];
                if (kk + 2 < cNS) p2 = pp[kk + 2];
            }
        }
        float4 vv = make_float4(0.f, 0.f, 0.f, 0.f);
        if (kt + vr < cNS) vv = *(const float4*)(Vbb + (size_t)(kt + vr) * cDH + vc);
        __syncthreads();
        Ps[pc + 0][pr] = p0; Ps[pc + 1][pr] = p1;
        Ps[pc + 2][pr] = p2; Ps[pc + 3][pr] = p3;
        *(float4*)&Vs[vr][vc] = vv;
        __syncthreads();
        #pragma unroll
        for (int k = 0; k < 16; k++) {
            float a0 = Ps[k][ty * 4 + 0], a1 = Ps[k][ty * 4 + 1];
            float a2 = Ps[k][ty * 4 + 2], a3 = Ps[k][ty * 4 + 3];
            float4 bb = *(const float4*)&Vs[k][tx * 4];
            acc[0][0] += a0 * bb.x; acc[0][1] += a0 * bb.y; acc[0][2] += a0 * bb.z; acc[0][3] += a0 * bb.w;
            acc[1][0] += a1 * bb.x; acc[1][1] += a1 * bb.y; acc[1][2] += a1 * bb.z; acc[1][3] += a1 * bb.w;
            acc[2][0] += a2 * bb.x; acc[2][1] += a2 * bb.y; acc[2][2] += a2 * bb.z; acc[2][3] += a2 * bb.w;
            acc[3][0] += a3 * bb.x; acc[3][1] += a3 * bb.y; acc[3][2] += a3 * bb.z; acc[3][3] += a3 * bb.w;
        }
    }
    #pragma unroll
    for (int i = 0; i < 4; i++) {
        int m = m0 + ty * 4 + i;
        if (m >= cND) continue;
        float* Ar = A + ((size_t)(b * cND + m)) * cD + h * cDH + tx * 4;
        Ar[0] = acc[i][0]; Ar[1] = acc[i][1]; Ar[2] = acc[i][2]; Ar[3] = acc[i][3];
    }
}

// ---------------------------------------------------------------------------
// Launch sequence
// ---------------------------------------------------------------------------
extern "C" void kernel_launch(void* const* d_in, const int* in_sizes, int n_in,
                              void* d_out, int out_size)
{
    (void)in_sizes; (void)n_in; (void)out_size;
    const float* x       = (const float*)d_in[0];
    const float* ctx     = (const float*)d_in[1];
    const float* sos     = (const float*)d_in[2];
    const float* ln1_g   = (const float*)d_in[3];
    const float* ln1_b   = (const float*)d_in[4];
    const float* W_attn  = (const float*)d_in[5];
    const float* b_attn  = (const float*)d_in[6];
    const float* W_ref   = (const float*)d_in[7];
    const float* b_ref   = (const float*)d_in[8];
    const float* W_proj  = (const float*)d_in[9];
    const float* b_proj  = (const float*)d_in[10];
    const float* ln2_g   = (const float*)d_in[11];
    const float* ln2_b   = (const float*)d_in[12];
    const float* W_fc    = (const float*)d_in[13];
    const float* b_fc    = (const float*)d_in[14];
    const float* W_mproj = (const float*)d_in[15];
    const float* b_mproj = (const float*)d_in[16];
    float* out = (float*)d_out;

    float *H, *HL, *QKV, *CKV, *Qb, *Kb, *Vb, *S, *A, *H2, *HL2, *FC;
    __nv_bfloat16 *As, *Bs;
    cudaGetSymbolAddress((void**)&H,   g_H);
    cudaGetSymbolAddress((void**)&HL,  g_HL);
    cudaGetSymbolAddress((void**)&QKV, g_QKV);
    cudaGetSymbolAddress((void**)&CKV, g_CKV);
    cudaGetSymbolAddress((void**)&Qb,  g_Q);
    cudaGetSymbolAddress((void**)&Kb,  g_K);
    cudaGetSymbolAddress((void**)&Vb,  g_V);
    cudaGetSymbolAddress((void**)&S,   g_S);
    cudaGetSymbolAddress((void**)&A,   g_A);
    cudaGetSymbolAddress((void**)&H2,  g_H2);
    cudaGetSymbolAddress((void**)&HL2, g_HL2);
    cudaGetSymbolAddress((void**)&FC,  g_FC);
    cudaGetSymbolAddress((void**)&As,  g_As);
    cudaGetSymbolAddress((void**)&Bs,  g_Bs);

    cudaFuncSetAttribute(tgemm, cudaFuncAttributeMaxDynamicSharedMemorySize, TG_SMEM);

    // 1. concat(sos, x) + LN1
    ln_kernel<<<cM, 256>>>(x, sos, ln1_g, ln1_b, H, HL, 1);

    // 2. qkv = ln1(h) @ W_attn + b_attn        [2050 x 2304], K3 = 2304
    act_split<<<(cM * cD + 255) / 256, 256>>>(HL, As, cM * cD, cD);
    w_split<<<dim3(3 * cD / 32, cD / 32), 256>>>(W_attn, Bs, cD, 3 * cD);
    tgemm<<<dim3(3 * cD / 128, 17), 256, TG_SMEM>>>(As, Bs, b_attn, nullptr, QKV,
                                                    cM, 3 * cD, 3 * cD, 0);

    // 3. ckv = context @ W_ref + b_ref         [512 x 1536]
    act_split<<<(cMC * cD + 255) / 256, 256>>>(ctx, As, cMC * cD, cD);
    w_split<<<dim3(2 * cD / 32, cD / 32), 256>>>(W_ref, Bs, cD, 2 * cD);
    tgemm<<<dim3(2 * cD / 128, 4), 256, TG_SMEM>>>(As, Bs, b_ref, nullptr, CKV,
                                                   cMC, 2 * cD, 3 * cD, 0);

    // 4. per-head gathers
    gather_kv<<<(cBH * cNS * cDH + 255) / 256, 256>>>(QKV, CKV, Kb, Vb);
    gather_q <<<(cBH * cND * cDH + 255) / 256, 256>>>(QKV, Qb);

    // 5. scores + mask, softmax, AV
    attn_scores<<<dim3((cNS + 63) / 64, (cND + 63) / 64, cBH), 256>>>(Qb, Kb, S);
    softmax_rows<<<cBH * cND, 256>>>(S);
    attn_av<<<dim3((cND + 63) / 64, cBH), 256>>>(S, Vb, A);

    // 6. h2 = h + attn @ W_proj + b_proj       [2050 x 768]
    act_split<<<(cM * cD + 255) / 256, 256>>>(A, As, cM * cD, cD);
    w_split<<<dim3(cD / 32, cD / 32), 256>>>(W_proj, Bs, cD, cD);
    tgemm<<<dim3(cD / 128, 17), 256, TG_SMEM>>>(As, Bs, b_proj, H, H2,
                                                cM, cD, 3 * cD, 2);

    // 7. LN2
    ln_kernel<<<cM, 256>>>(H2, nullptr, ln2_g, ln2_b, nullptr, HL2, 0);

    // 8. fc = gelu(ln2(h2) @ W_fc + b_fc)      [2050 x 3072]
    act_split<<<(cM * cD + 255) / 256, 256>>>(HL2, As, cM * cD, cD);
    w_split<<<dim3(4 * cD / 32, cD / 32), 256>>>(W_fc, Bs, cD, 4 * cD);
    tgemm<<<dim3(4 * cD / 128, 17), 256, TG_SMEM>>>(As, Bs, b_fc, nullptr, FC,
                                                    cM, 4 * cD, 3 * cD, 1);

    // 9. out = (h2 + fc @ W_mproj + b_mproj)[:, 1:, :]   K3 = 9216
    act_split<<<(cM * 4 * cD + 255) / 256, 256>>>(FC, As, cM * 4 * cD, 4 * cD);
    w_split<<<dim3(cD / 32, 4 * cD / 32), 256>>>(W_mproj, Bs, 4 * cD, cD);
    tgemm<<<dim3(cD / 128, 17), 256, TG_SMEM>>>(As, Bs, b_mproj, H2, out,
                                                cM, cD, 12 * cD, 3);
}

// round 10
// speedup vs baseline: 1.8722x; 1.1460x over previous
#include <cuda_runtime.h>
#include <cuda_bf16.h>
#include <math.h>
#include <stdint.h>

// ---------------------------------------------------------------------------
// Problem constants (CoconBlock: B=2, S=1024, Sc=256, D=768, H=12, dh=64)
// ---------------------------------------------------------------------------
constexpr int cD   = 768;
constexpr int cH   = 12;
constexpr int cDH  = 64;
constexpr int cB   = 2;
constexpr int cS   = 1024;
constexpr int cSC  = 256;
constexpr int cND  = cS + 1;          // 1025 queries per batch (sos + seq)
constexpr int cNS  = cSC + cND;       // 1281 keys per batch
constexpr int cM   = cB * cND;        // 2050 rows in main activation
constexpr int cMC  = cB * cSC;        // 512 context rows
constexpr int cBH  = cB * cH;         // 24 (batch, head) pairs
constexpr int cMPAD = 2176;           // 17 * 128 (padded row count for MMA tiles)

// attention padded dims
constexpr int NDP  = 1152;            // 9 * 128 padded queries
constexpr int NSP  = 1408;            // 11 * 128 padded keys
constexpr int K3Q  = 192;             // 3 * dh (split)
constexpr int K3AV = 3 * NSP;         // 4224 (split keys for AV)

// ---------------------------------------------------------------------------
// Scratch (static __device__ arrays, zero-initialized; padding regions are
// never written so they stay zero across graph replays)
// ---------------------------------------------------------------------------
__device__ float g_H  [(size_t)cM * cD];
__device__ float g_HL [(size_t)cM * cD];
__device__ float g_QKV[(size_t)cM * 3 * cD];
__device__ float g_CKV[(size_t)cMC * 2 * cD];
__device__ float g_A  [(size_t)cM * cD];
__device__ float g_H2 [(size_t)cM * cD];
__device__ float g_HL2[(size_t)cM * cD];
__device__ float g_FC [(size_t)cM * 4 * cD];
// bf16 split operands (reused per GEMM, sequential)
__device__ __nv_bfloat16 g_As[(size_t)cMPAD * 3 * 3072];    // A' [Mpad, 3K], K<=3072
__device__ __nv_bfloat16 g_Bs[(size_t)3072 * 2304];          // B' [N, 3K]
// attention buffers
__device__ __nv_bfloat16 g_Qs [(size_t)cBH * NDP * K3Q];     // split Q
__device__ __nv_bfloat16 g_Ks [(size_t)cBH * NSP * K3Q];     // split K
__device__ __nv_bfloat16 g_Vts[(size_t)cBH * cDH * K3AV];    // split V^T
__device__ float         g_Sp [(size_t)cBH * NDP * NSP];     // scores (padded)
__device__ __nv_bfloat16 g_Ps [(size_t)cBH * NDP * K3AV];    // split probs

// ---------------------------------------------------------------------------
// Small helpers
// ---------------------------------------------------------------------------
__device__ __forceinline__ float gelu_new(float x) {
    float x3 = x * x * x;
    return 0.5f * x * (1.0f + tanhf(0.7978845608028654f * (x + 0.044715f * x3)));
}
__device__ __forceinline__ uint32_t smem_u32(const void* p) {
    uint32_t a;
    asm("{ .reg .u64 t; cvta.to.shared.u64 t, %1; cvt.u32.u64 %0, t; }" : "=r"(a) : "l"(p));
    return a;
}
__device__ __forceinline__ void cp16(uint32_t s, const void* g) {
    asm volatile("cp.async.cg.shared.global [%0], [%1], 16;\n"
                 :: "r"(s), "l"(__cvta_generic_to_global(g)) : "memory");
}
__device__ __forceinline__ void ldsm_x4(uint32_t& r0, uint32_t& r1, uint32_t& r2,
                                        uint32_t& r3, uint32_t addr) {
    asm volatile("ldmatrix.sync.aligned.m8n8.x4.shared.b16 {%0,%1,%2,%3}, [%4];"
                 : "=r"(r0), "=r"(r1), "=r"(r2), "=r"(r3) : "r"(addr));
}
__device__ __forceinline__ void ldsm_x2(uint32_t& r0, uint32_t& r1, uint32_t addr) {
    asm volatile("ldmatrix.sync.aligned.m8n8.x2.shared.b16 {%0,%1}, [%2];"
                 : "=r"(r0), "=r"(r1) : "r"(addr));
}
__device__ __forceinline__ void mma16816(float* c, const uint32_t* a, const uint32_t* b) {
    asm volatile(
        "mma.sync.aligned.m16n8k16.row.col.f32.bf16.bf16.f32 "
        "{%0,%1,%2,%3}, {%4,%5,%6,%7}, {%8,%9}, {%0,%1,%2,%3};"
        : "+f"(c[0]), "+f"(c[1]), "+f"(c[2]), "+f"(c[3])
        : "r"(a[0]), "r"(a[1]), "r"(a[2]), "r"(a[3]), "r"(b[0]), "r"(b[1]));
}

// ---------------------------------------------------------------------------
// Split conversion kernels  (A'=[hi,lo,hi], B'=[hi,hi,lo] per k)
// ---------------------------------------------------------------------------
__global__ __launch_bounds__(256) void act_split(
    const float* __restrict__ X, __nv_bfloat16* __restrict__ Y, int MK, int K)
{
    int idx = blockIdx.x * 256 + threadIdx.x;
    if (idx >= MK) return;
    int m = idx / K, k = idx % K;
    float x = X[idx];
    __nv_bfloat16 hi = __float2bfloat16(x);
    __nv_bfloat16 lo = __float2bfloat16(x - __bfloat162float(hi));
    size_t o = (size_t)m * (3 * K) + 3 * k;
    Y[o] = hi; Y[o + 1] = lo; Y[o + 2] = hi;
}

__global__ __launch_bounds__(256) void w_split(
    const float* __restrict__ W, __nv_bfloat16* __restrict__ Y, int K, int N)
{
    __shared__ float t[32][33];
    int k0 = blockIdx.y * 32, n0 = blockIdx.x * 32;
    int tid = threadIdx.x;
    #pragma unroll
    for (int p = 0; p < 4; p++) {
        int idx = p * 256 + tid;
        int kk = idx >> 5, nn = idx & 31;
        t[kk][nn] = W[(size_t)(k0 + kk) * N + n0 + nn];
    }
    __syncthreads();
    #pragma unroll
    for (int p = 0; p < 4; p++) {
        int idx = p * 256 + tid;
        int nn = idx >> 5, kk = idx & 31;
        float x = t[kk][nn];
        __nv_bfloat16 hi = __float2bfloat16(x);
        __nv_bfloat16 lo = __float2bfloat16(x - __bfloat162float(hi));
        size_t o = (size_t)(n0 + nn) * (3 * (size_t)K) + 3 * (size_t)(k0 + kk);
        Y[o] = hi; Y[o + 1] = hi; Y[o + 2] = lo;
    }
}

// ---------------------------------------------------------------------------
// HMMA GEMM: C[M,N] = A'[M,K3] x B'[N,K3]^T (+bias, +epilogue)
// 128x128 tile, 256 threads (8 warps 2x4; 64x32 per warp), BK=64,
// double-buffered cp.async, 144B pitch.
// mode: 0 none, 1 gelu_new, 2 +R, 3 +R then write with sos row dropped.
// ---------------------------------------------------------------------------
constexpr int TG_PITCH = 144;
constexpr int TG_STG   = 128 * TG_PITCH;      // 18432
constexpr int TG_SMEM  = 4 * TG_STG + 128;

__global__ __launch_bounds__(256, 2) void tgemm(
    const __nv_bfloat16* __restrict__ A3, const __nv_bfloat16* __restrict__ B3,
    const float* __restrict__ bias, const float* __restrict__ R,
    float* __restrict__ C, int M, int N, int K3, int mode)
{
    extern __shared__ char dynraw[];
    char* sb = (char*)(((uintptr_t)dynraw + 127) & ~(uintptr_t)127);
    const uint32_t sA0 = smem_u32(sb);
    const uint32_t sB0 = sA0 + 2 * TG_STG;

    const int tid  = threadIdx.x;
    const int wid  = tid >> 5;
    const int lane = tid & 31;
    const int g    = lane >> 2;
    const int tg   = lane & 3;
    const int wm   = wid >> 2;
    const int wn   = wid & 3;
    const int row0 = blockIdx.y * 128;
    const int col0 = blockIdx.x * 128;

    uint32_t soff[4];
    const __nv_bfloat16 *Ag[4], *Bg[4];
    #pragma unroll
    for (int p = 0; p < 4; p++) {
        int idx = p * 256 + tid;
        int row = idx >> 3, seg = idx & 7;
        soff[p] = (uint32_t)(row * TG_PITCH + seg * 16);
        Ag[p] = A3 + (size_t)(row0 + row) * K3 + seg * 8;
        Bg[p] = B3 + (size_t)(col0 + row) * K3 + seg * 8;
    }

    const uint32_t aoff = (uint32_t)((wm * 64 + (lane & 15)) * TG_PITCH + (lane >> 4) * 16);
    const uint32_t boff = (uint32_t)((wn * 32 + (lane & 7)) * TG_PITCH + ((lane >> 3) & 1) * 16);

    float c[4][4][4];
    #pragma unroll
    for (int mi = 0; mi < 4; mi++)
        #pragma unroll
        for (int ni = 0; ni < 4; ni++)
            #pragma unroll
            for (int e = 0; e < 4; e++) c[mi][ni][e] = 0.f;

    const int nch = K3 >> 6;

    #pragma unroll
    for (int p = 0; p < 4; p++) {
        cp16(sA0 + soff[p], Ag[p]);
        cp16(sB0 + soff[p], Bg[p]);
    }
    asm volatile("cp.async.commit_group;" ::: "memory");

    for (int i = 0; i < nch; i++) {
        const int st = i & 1;
        if (i + 1 < nch) {
            const int st2 = (i + 1) & 1;
            const int ko = (i + 1) * 64;
            #pragma unroll
            for (int p = 0; p < 4; p++) {
                cp16(sA0 + st2 * TG_STG + soff[p], Ag[p] + ko);
                cp16(sB0 + st2 * TG_STG + soff[p], Bg[p] + ko);
            }
            asm volatile("cp.async.commit_group;" ::: "memory");
            asm volatile("cp.async.wait_group 1;" ::: "memory");
        } else {
            asm volatile("cp.async.wait_group 0;" ::: "memory");
        }
        __syncthreads();

        const uint32_t sa = sA0 + st * TG_STG + aoff;
        const uint32_t sbb = sB0 + st * TG_STG + boff;
        #pragma unroll
        for (int ks = 0; ks < 4; ks++) {
            uint32_t a[4][4], b[4][2];
            #pragma unroll
            for (int mi = 0; mi < 4; mi++)
                ldsm_x4(a[mi][0], a[mi][1], a[mi][2], a[mi][3],
                        sa + (uint32_t)(mi * 16 * TG_PITCH + ks * 32));
            #pragma unroll
            for (int ni = 0; ni < 4; ni++)
                ldsm_x2(b[ni][0], b[ni][1],
                        sbb + (uint32_t)(ni * 8 * TG_PITCH + ks * 32));
            #pragma unroll
            for (int mi = 0; mi < 4; mi++)
                #pragma unroll
                for (int ni = 0; ni < 4; ni++)
                    mma16816(c[mi][ni], a[mi], b[ni]);
        }
        __syncthreads();
    }

    #pragma unroll
    for (int mi = 0; mi < 4; mi++) {
        #pragma unroll
        for (int half = 0; half < 2; half++) {
            int rg = row0 + wm * 64 + mi * 16 + g + half * 8;
            if (rg >= M) continue;
            float* crow;
            if (mode == 3) {
                int t = rg % cND;
                if (t == 0) continue;
                crow = C + ((size_t)((rg / cND) * cS + (t - 1))) * N;
            } else {
                crow = C + (size_t)rg * N;
            }
            #pragma unroll
            for (int ni = 0; ni < 4; ni++) {
                int cg = col0 + wn * 32 + ni * 8 + 2 * tg;
                float v0 = c[mi][ni][half * 2 + 0] + __ldg(&bias[cg]);
                float v1 = c[mi][ni][half * 2 + 1] + __ldg(&bias[cg + 1]);
                if (mode == 1) { v0 = gelu_new(v0); v1 = gelu_new(v1); }
                else if (mode >= 2) {
                    v0 += R[(size_t)rg * N + cg];
                    v1 += R[(size_t)rg * N + cg + 1];
                }
                *(float2*)(crow + cg) = make_float2(v0, v1);
            }
        }
    }
}

// ---------------------------------------------------------------------------
// scores_mma: S[bh, m, n] (padded NDP x NSP) = Qs x Ks^T with mask epilogue.
// Same structure as tgemm; K3 = 192 (3 chunks); z = bh.
// ---------------------------------------------------------------------------
__global__ __launch_bounds__(256, 2) void scores_mma(
    const __nv_bfloat16* __restrict__ Qs, const __nv_bfloat16* __restrict__ Ks,
    float* __restrict__ S)
{
    extern __shared__ char dynraw[];
    char* sb = (char*)(((uintptr_t)dynraw + 127) & ~(uintptr_t)127);
    const uint32_t sA0 = smem_u32(sb);
    const uint32_t sB0 = sA0 + 2 * TG_STG;

    const int tid  = threadIdx.x;
    const int wid  = tid >> 5;
    const int lane = tid & 31;
    const int g    = lane >> 2;
    const int tg   = lane & 3;
    const int wm   = wid >> 2;
    const int wn   = wid & 3;
    const int bh   = blockIdx.z;
    const int row0 = blockIdx.y * 128;
    const int col0 = blockIdx.x * 128;

    const __nv_bfloat16* A3 = Qs + (size_t)bh * NDP * K3Q;
    const __nv_bfloat16* B3 = Ks + (size_t)bh * NSP * K3Q;

    uint32_t soff[4];
    const __nv_bfloat16 *Ag[4], *Bg[4];
    #pragma unroll
    for (int p = 0; p < 4; p++) {
        int idx = p * 256 + tid;
        int row = idx >> 3, seg = idx & 7;
        soff[p] = (uint32_t)(row * TG_PITCH + seg * 16);
        Ag[p] = A3 + (size_t)(row0 + row) * K3Q + seg * 8;
        Bg[p] = B3 + (size_t)(col0 + row) * K3Q + seg * 8;
    }
    const uint32_t aoff = (uint32_t)((wm * 64 + (lane & 15)) * TG_PITCH + (lane >> 4) * 16);
    const uint32_t boff = (uint32_t)((wn * 32 + (lane & 7)) * TG_PITCH + ((lane >> 3) & 1) * 16);

    float c[4][4][4];
    #pragma unroll
    for (int mi = 0; mi < 4; mi++)
        #pragma unroll
        for (int ni = 0; ni < 4; ni++)
            #pragma unroll
            for (int e = 0; e < 4; e++) c[mi][ni][e] = 0.f;

    #pragma unroll
    for (int p = 0; p < 4; p++) {
        cp16(sA0 + soff[p], Ag[p]);
        cp16(sB0 + soff[p], Bg[p]);
    }
    asm volatile("cp.async.commit_group;" ::: "memory");

    #pragma unroll
    for (int i = 0; i < 3; i++) {
        const int st = i & 1;
        if (i + 1 < 3) {
            const int st2 = (i + 1) & 1;
            const int ko = (i + 1) * 64;
            #pragma unroll
            for (int p = 0; p < 4; p++) {
                cp16(sA0 + st2 * TG_STG + soff[p], Ag[p] + ko);
                cp16(sB0 + st2 * TG_STG + soff[p], Bg[p] + ko);
            }
            asm volatile("cp.async.commit_group;" ::: "memory");
            asm volatile("cp.async.wait_group 1;" ::: "memory");
        } else {
            asm volatile("cp.async.wait_group 0;" ::: "memory");
        }
        __syncthreads();
        const uint32_t sa = sA0 + st * TG_STG + aoff;
        const uint32_t sbb = sB0 + st * TG_STG + boff;
        #pragma unroll
        for (int ks = 0; ks < 4; ks++) {
            uint32_t a[4][4], b[4][2];
            #pragma unroll
            for (int mi = 0; mi < 4; mi++)
                ldsm_x4(a[mi][0], a[mi][1], a[mi][2], a[mi][3],
                        sa + (uint32_t)(mi * 16 * TG_PITCH + ks * 32));
            #pragma unroll
            for (int ni = 0; ni < 4; ni++)
                ldsm_x2(b[ni][0], b[ni][1],
                        sbb + (uint32_t)(ni * 8 * TG_PITCH + ks * 32));
            #pragma unroll
            for (int mi = 0; mi < 4; mi++)
                #pragma unroll
                for (int ni = 0; ni < 4; ni++)
                    mma16816(c[mi][ni], a[mi], b[ni]);
        }
        __syncthreads();
    }

    float* Sb = S + (size_t)bh * NDP * NSP;
    const float scale = 0.125f;   // 1/sqrt(64)
    #pragma unroll
    for (int mi = 0; mi < 4; mi++) {
        #pragma unroll
        for (int half = 0; half < 2; half++) {
            int rg = row0 + wm * 64 + mi * 16 + g + half * 8;
            float* Sr = Sb + (size_t)rg * NSP;
            #pragma unroll
            for (int ni = 0; ni < 4; ni++) {
                int cg = col0 + wn * 32 + ni * 8 + 2 * tg;
                float v0 = (cg     <= rg + cSC) ? c[mi][ni][half * 2 + 0] * scale : -10000.0f;
                float v1 = (cg + 1 <= rg + cSC) ? c[mi][ni][half * 2 + 1] * scale : -10000.0f;
                *(float2*)(Sr + cg) = make_float2(v0, v1);
            }
        }
    }
}

// ---------------------------------------------------------------------------
// av_mma: A_merged = P' x Vt'^T.  128x64 tile, 8 warps 4x2 (32x32 per warp),
// K3 = 4224 (66 chunks).
// ---------------------------------------------------------------------------
constexpr int AV_BSTG = 64 * TG_PITCH;                  // 9216
constexpr int AV_SMEM = 2 * TG_STG + 2 * AV_BSTG + 128; // ~55.5KB

__global__ __launch_bounds__(256, 2) void av_mma(
    const __nv_bfloat16* __restrict__ P3, const __nv_bfloat16* __restrict__ V3,
    float* __restrict__ A)
{
    extern __shared__ char dynraw[];
    char* sb = (char*)(((uintptr_t)dynraw + 127) & ~(uintptr_t)127);
    const uint32_t sA0 = smem_u32(sb);
    const uint32_t sB0 = sA0 + 2 * TG_STG;

    const int tid  = threadIdx.x;
    const int wid  = tid >> 5;
    const int lane = tid & 31;
    const int g    = lane >> 2;
    const int tg   = lane & 3;
    const int wm   = wid >> 1;          // 0..3 (32 rows each)
    const int wn   = wid & 1;           // 0..1 (32 cols each)
    const int bh   = blockIdx.y;
    const int row0 = blockIdx.x * 128;

    const __nv_bfloat16* A3 = P3 + (size_t)bh * NDP * K3AV;
    const __nv_bfloat16* B3 = V3 + (size_t)bh * cDH * K3AV;

    uint32_t soffA[4];
    const __nv_bfloat16* Ag[4];
    #pragma unroll
    for (int p = 0; p < 4; p++) {
        int idx = p * 256 + tid;
        int row = idx >> 3, seg = idx & 7;
        soffA[p] = (uint32_t)(row * TG_PITCH + seg * 16);
        Ag[p] = A3 + (size_t)(row0 + row) * K3AV + seg * 8;
    }
    uint32_t soffB[2];
    const __nv_bfloat16* Bg[2];
    #pragma unroll
    for (int p = 0; p < 2; p++) {
        int idx = p * 256 + tid;        // 0..511
        int row = idx >> 3, seg = idx & 7;
        soffB[p] = (uint32_t)(row * TG_PITCH + seg * 16);
        Bg[p] = B3 + (size_t)row * K3AV + seg * 8;
    }

    const uint32_t aoff = (uint32_t)((wm * 32 + (lane & 15)) * TG_PITCH + (lane >> 4) * 16);
    const uint32_t boff = (uint32_t)((wn * 32 + (lane & 7)) * TG_PITCH + ((lane >> 3) & 1) * 16);

    float c[2][4][4];
    #pragma unroll
    for (int mi = 0; mi < 2; mi++)
        #pragma unroll
        for (int ni = 0; ni < 4; ni++)
            #pragma unroll
            for (int e = 0; e < 4; e++) c[mi][ni][e] = 0.f;

    const int nch = K3AV >> 6;   // 66

    #pragma unroll
    for (int p = 0; p < 4; p++) cp16(sA0 + soffA[p], Ag[p]);
    #pragma unroll
    for (int p = 0; p < 2; p++) cp16(sB0 + soffB[p], Bg[p]);
    asm volatile("cp.async.commit_group;" ::: "memory");

    for (int i = 0; i < nch; i++) {
        const int st = i & 1;
        if (i + 1 < nch) {
            const int st2 = (i + 1) & 1;
            const int ko = (i + 1) * 64;
            #pragma unroll
            for (int p = 0; p < 4; p++) cp16(sA0 + st2 * TG_STG + soffA[p], Ag[p] + ko);
            #pragma unroll
            for (int p = 0; p < 2; p++) cp16(sB0 + st2 * AV_BSTG + soffB[p], Bg[p] + ko);
            asm volatile("cp.async.commit_group;" ::: "memory");
            asm volatile("cp.async.wait_group 1;" ::: "memory");
        } else {
            asm volatile("cp.async.wait_group 0;" ::: "memory");
        }
        __syncthreads();

        const uint32_t sa = sA0 + st * TG_STG + aoff;
        const uint32_t sbb = sB0 + st * AV_BSTG + boff;
        #pragma unroll
        for (int ks = 0; ks < 4; ks++) {
            uint32_t a[2][4], b[4][2];
            #pragma unroll
            for (int mi = 0; mi < 2; mi++)
                ldsm_x4(a[mi][0], a[mi][1], a[mi][2], a[mi][3],
                        sa + (uint32_t)(mi * 16 * TG_PITCH + ks * 32));
            #pragma unroll
            for (int ni = 0; ni < 4; ni++)
                ldsm_x2(b[ni][0], b[ni][1],
                        sbb + (uint32_t)(ni * 8 * TG_PITCH + ks * 32));
            #pragma unroll
            for (int mi = 0; mi < 2; mi++)
                #pragma unroll
                for (int ni = 0; ni < 4; ni++)
                    mma16816(c[mi][ni], a[mi], b[ni]);
        }
        __syncthreads();
    }

    const int b_ = bh / cH, h = bh % cH;
    #pragma unroll
    for (int mi = 0; mi < 2; mi++) {
        #pragma unroll
        for (int half = 0; half < 2; half++) {
            int rg = row0 + wm * 32 + mi * 16 + g + half * 8;
            if (rg >= cND) continue;
            float* Ar = A + ((size_t)(b_ * cND + rg)) * cD + h * cDH;
            #pragma unroll
            for (int ni = 0; ni < 4; ni++) {
                int cg = wn * 32 + ni * 8 + 2 * tg;
                *(float2*)(Ar + cg) =
                    make_float2(c[mi][ni][half * 2 + 0], c[mi][ni][half * 2 + 1]);
            }
        }
    }
}

// ---------------------------------------------------------------------------
// LayerNorm (optionally fused with sos-concat gather)
// ---------------------------------------------------------------------------
__global__ __launch_bounds__(256) void ln_kernel(
    const float* __restrict__ in, const float* __restrict__ sos,
    const float* __restrict__ gamma, const float* __restrict__ beta,
    float* __restrict__ Hout, float* __restrict__ HLout, int concat)
{
    int r   = blockIdx.x;
    int tid = threadIdx.x;
    const float* src;
    if (concat) {
        int b = r / cND, t = r % cND;
        src = (t == 0) ? sos : in + ((size_t)b * cS + (t - 1)) * cD;
    } else {
        src = in + (size_t)r * cD;
    }
    float v0 = src[tid], v1 = src[tid + 256], v2 = src[tid + 512];
    float s  = v0 + v1 + v2;
    float ss = v0 * v0 + v1 * v1 + v2 * v2;

    __shared__ float sb[8], sb2[8];
    #pragma unroll
    for (int o = 16; o; o >>= 1) {
        s  += __shfl_xor_sync(0xffffffffu, s,  o);
        ss += __shfl_xor_sync(0xffffffffu, ss, o);
    }
    int lane = tid & 31, w = tid >> 5;
    if (lane == 0) { sb[w] = s; sb2[w] = ss; }
    __syncthreads();
    if (tid == 0) {
        float a = 0.f, c = 0.f;
        #pragma unroll
        for (int i = 0; i < 8; i++) { a += sb[i]; c += sb2[i]; }
        sb[0] = a; sb2[0] = c;
    }
    __syncthreads();
    float mean = sb[0] * (1.0f / 768.0f);
    float var  = sb2[0] * (1.0f / 768.0f) - mean * mean;
    float inv  = rsqrtf(var + 1e-5f);

    if (concat) {
        float* hr = Hout + (size_t)r * cD;
        hr[tid] = v0; hr[tid + 256] = v1; hr[tid + 512] = v2;
    }
    float* hlr = HLout + (size_t)r * cD;
    hlr[tid      ] = (v0 - mean) * inv * gamma[tid      ] + beta[tid      ];
    hlr[tid + 256] = (v1 - mean) * inv * gamma[tid + 256] + beta[tid + 256];
    hlr[tid + 512] = (v2 - mean) * inv * gamma[tid + 512] + beta[tid + 512];
}

// ---------------------------------------------------------------------------
// Split gathers for attention
// ---------------------------------------------------------------------------
__global__ void gather_q_split(const float* __restrict__ QKV, __nv_bfloat16* __restrict__ Qs)
{
    int idx = blockIdx.x * blockDim.x + threadIdx.x;
    if (idx >= cBH * cND * cDH) return;
    int d    = idx & (cDH - 1);
    int rest = idx >> 6;
    int t    = rest % cND;
    int bh   = rest / cND;
    int b = bh / cH, h = bh % cH;
    float x = QKV[((size_t)(b * cND + t)) * (3 * cD) + h * cDH + d];
    __nv_bfloat16 hi = __float2bfloat16(x);
    __nv_bfloat16 lo = __float2bfloat16(x - __bfloat162float(hi));
    size_t o = ((size_t)bh * NDP + t) * K3Q + 3 * d;
    Qs[o] = hi; Qs[o + 1] = lo; Qs[o + 2] = hi;
}

__global__ void gather_k_split(const float* __restrict__ QKV, const float* __restrict__ CKV,
                               __nv_bfloat16* __restrict__ Ks)
{
    int idx = blockIdx.x * blockDim.x + threadIdx.x;
    if (idx >= cBH * cNS * cDH) return;
    int d    = idx & (cDH - 1);
    int rest = idx >> 6;
    int j    = rest % cNS;
    int bh   = rest / cNS;
    int b = bh / cH, h = bh % cH;
    float kv;
    if (j < cSC)
        kv = CKV[((size_t)(b * cSC + j)) * (2 * cD) + h * cDH + d];
    else
        kv = QKV[((size_t)(b * cND + (j - cSC))) * (3 * cD) + cD + h * cDH + d];
    __nv_bfloat16 hi = __float2bfloat16(kv);
    __nv_bfloat16 lo = __float2bfloat16(kv - __bfloat162float(hi));
    size_t o = ((size_t)bh * NSP + j) * K3Q + 3 * d;
    Ks[o] = hi; Ks[o + 1] = hi; Ks[o + 2] = lo;
}

// V^T split: Vts[bh][d][3j] = [hi,hi,lo] of V[j,d]; j fastest for coalesced writes
__global__ void gather_vt_split(const float* __restrict__ QKV, const float* __restrict__ CKV,
                                __nv_bfloat16* __restrict__ Vts)
{
    int idx = blockIdx.x * blockDim.x + threadIdx.x;
    if (idx >= cBH * cDH * cNS) return;
    int j    = idx % cNS;
    int rest = idx / cNS;
    int d    = rest & (cDH - 1);
    int bh   = rest >> 6;
    int b = bh / cH, h = bh % cH;
    float vv;
    if (j < cSC)
        vv = CKV[((size_t)(b * cSC + j)) * (2 * cD) + cD + h * cDH + d];
    else
        vv = QKV[((size_t)(b * cND + (j - cSC))) * (3 * cD) + 2 * cD + h * cDH + d];
    __nv_bfloat16 hi = __float2bfloat16(vv);
    __nv_bfloat16 lo = __float2bfloat16(vv - __bfloat162float(hi));
    size_t o = ((size_t)bh * cDH + d) * K3AV + 3 * j;
    Vts[o] = hi; Vts[o + 1] = hi; Vts[o + 2] = lo;
}

// ---------------------------------------------------------------------------
// Softmax over padded rows; writes split-bf16 probs [hi,lo,hi] + zero padding
// ---------------------------------------------------------------------------
__global__ __launch_bounds__(256) void softmax_split(
    const float* __restrict__ S, __nv_bfloat16* __restrict__ Ps)
{
    int r  = blockIdx.x;                 // 0 .. 24*1025-1
    int bh = r / cND, m = r % cND;
    const float* p = S + ((size_t)bh * NDP + m) * NSP;
    __nv_bfloat16* out = Ps + ((size_t)bh * NDP + m) * K3AV;
    int tid = threadIdx.x;

    float vals[6];
    float mx = -3.4e38f;
    #pragma unroll
    for (int it = 0; it < 6; it++) {
        int i = tid + it * 256;
        float v = (i < cNS) ? p[i] : -3.4e38f;
        vals[it] = v;
        mx = fmaxf(mx, v);
    }
    __shared__ float sb[8];
    #pragma unroll
    for (int o = 16; o; o >>= 1) mx = fmaxf(mx, __shfl_xor_sync(0xffffffffu, mx, o));
    if ((tid & 31) == 0) sb[tid >> 5] = mx;
    __syncthreads();
    if (tid < 32) {
        float m2 = (tid < 8) ? sb[tid] : -3.4e38f;
        #pragma unroll
        for (int o = 4; o; o >>= 1) m2 = fmaxf(m2, __shfl_xor_sync(0xffffffffu, m2, o));
        if (tid == 0) sb[0] = m2;
    }
    __syncthreads();
    float bmax = sb[0];
    __syncthreads();

    float s = 0.f;
    #pragma unroll
    for (int it = 0; it < 6; it++) {
        int i = tid + it * 256;
        if (i < cNS) {
            float e = __expf(vals[it] - bmax);
            vals[it] = e;
            s += e;
        }
    }
    #pragma unroll
    for (int o = 16; o; o >>= 1) s += __shfl_xor_sync(0xffffffffu, s, o);
    if ((tid & 31) == 0) sb[tid >> 5] = s;
    __syncthreads();
    if (tid < 32) {
        float s2 = (tid < 8) ? sb[tid] : 0.f;
        #pragma unroll
        for (int o = 4; o; o >>= 1) s2 += __shfl_xor_sync(0xffffffffu, s2, o);
        if (tid == 0) sb[0] = s2;
    }
    __syncthreads();
    float inv = 1.0f / sb[0];
    #pragma unroll
    for (int it = 0; it < 6; it++) {
        int i = tid + it * 256;
        if (i >= NSP) continue;
        float v = (i < cNS) ? vals[it] * inv : 0.f;
        __nv_bfloat16 hi = __float2bfloat16(v);
        __nv_bfloat16 lo = __float2bfloat16(v - __bfloat162float(hi));
        out[3 * i] = hi; out[3 * i + 1] = lo; out[3 * i + 2] = hi;
    }
}

// ---------------------------------------------------------------------------
// Launch sequence
// ---------------------------------------------------------------------------
extern "C" void kernel_launch(void* const* d_in, const int* in_sizes, int n_in,
                              void* d_out, int out_size)
{
    (void)in_sizes; (void)n_in; (void)out_size;
    const float* x       = (const float*)d_in[0];
    const float* ctx     = (const float*)d_in[1];
    const float* sos     = (const float*)d_in[2];
    const float* ln1_g   = (const float*)d_in[3];
    const float* ln1_b   = (const float*)d_in[4];
    const float* W_attn  = (const float*)d_in[5];
    const float* b_attn  = (const float*)d_in[6];
    const float* W_ref   = (const float*)d_in[7];
    const float* b_ref   = (const float*)d_in[8];
    const float* W_proj  = (const float*)d_in[9];
    const float* b_proj  = (const float*)d_in[10];
    const float* ln2_g   = (const float*)d_in[11];
    const float* ln2_b   = (const float*)d_in[12];
    const float* W_fc    = (const float*)d_in[13];
    const float* b_fc    = (const float*)d_in[14];
    const float* W_mproj = (const float*)d_in[15];
    const float* b_mproj = (const float*)d_in[16];
    float* out = (float*)d_out;

    float *H, *HL, *QKV, *CKV, *A, *H2, *HL2, *FC, *Sp;
    __nv_bfloat16 *As, *Bs, *Qs, *Ks, *Vts, *Ps;
    cudaGetSymbolAddress((void**)&H,   g_H);
    cudaGetSymbolAddress((void**)&HL,  g_HL);
    cudaGetSymbolAddress((void**)&QKV, g_QKV);
    cudaGetSymbolAddress((void**)&CKV, g_CKV);
    cudaGetSymbolAddress((void**)&A,   g_A);
    cudaGetSymbolAddress((void**)&H2,  g_H2);
    cudaGetSymbolAddress((void**)&HL2, g_HL2);
    cudaGetSymbolAddress((void**)&FC,  g_FC);
    cudaGetSymbolAddress((void**)&Sp,  g_Sp);
    cudaGetSymbolAddress((void**)&As,  g_As);
    cudaGetSymbolAddress((void**)&Bs,  g_Bs);
    cudaGetSymbolAddress((void**)&Qs,  g_Qs);
    cudaGetSymbolAddress((void**)&Ks,  g_Ks);
    cudaGetSymbolAddress((void**)&Vts, g_Vts);
    cudaGetSymbolAddress((void**)&Ps,  g_Ps);

    cudaFuncSetAttribute(tgemm,      cudaFuncAttributeMaxDynamicSharedMemorySize, TG_SMEM);
    cudaFuncSetAttribute(scores_mma, cudaFuncAttributeMaxDynamicSharedMemorySize, TG_SMEM);
    cudaFuncSetAttribute(av_mma,     cudaFuncAttributeMaxDynamicSharedMemorySize, AV_SMEM);

    // 1. concat(sos, x) + LN1
    ln_kernel<<<cM, 256>>>(x, sos, ln1_g, ln1_b, H, HL, 1);

    // 2. qkv = ln1(h) @ W_attn + b_attn
    act_split<<<(cM * cD + 255) / 256, 256>>>(HL, As, cM * cD, cD);
    w_split<<<dim3(3 * cD / 32, cD / 32), 256>>>(W_attn, Bs, cD, 3 * cD);
    tgemm<<<dim3(3 * cD / 128, 17), 256, TG_SMEM>>>(As, Bs, b_attn, nullptr, QKV,
                                                    cM, 3 * cD, 3 * cD, 0);

    // 3. ckv = context @ W_ref + b_ref
    act_split<<<(cMC * cD + 255) / 256, 256>>>(ctx, As, cMC * cD, cD);
    w_split<<<dim3(2 * cD / 32, cD / 32), 256>>>(W_ref, Bs, cD, 2 * cD);
    tgemm<<<dim3(2 * cD / 128, 4), 256, TG_SMEM>>>(As, Bs, b_ref, nullptr, CKV,
                                                   cMC, 2 * cD, 3 * cD, 0);

    // 4. split gathers for attention
    gather_q_split<<<(cBH * cND * cDH + 255) / 256, 256>>>(QKV, Qs);
    gather_k_split<<<(cBH * cNS * cDH + 255) / 256, 256>>>(QKV, CKV, Ks);
    gather_vt_split<<<(cBH * cDH * cNS + 255) / 256, 256>>>(QKV, CKV, Vts);

    // 5. attention on tensor pipe
    scores_mma<<<dim3(NSP / 128, NDP / 128, cBH), 256, TG_SMEM>>>(Qs, Ks, Sp);
    softmax_split<<<cBH * cND, 256>>>(Sp, Ps);
    av_mma<<<dim3(NDP / 128, cBH), 256, AV_SMEM>>>(Ps, Vts, A);

    // 6. h2 = h + attn @ W_proj + b_proj
    act_split<<<(cM * cD + 255) / 256, 256>>>(A, As, cM * cD, cD);
    w_split<<<dim3(cD / 32, cD / 32), 256>>>(W_proj, Bs, cD, cD);
    tgemm<<<dim3(cD / 128, 17), 256, TG_SMEM>>>(As, Bs, b_proj, H, H2,
                                                cM, cD, 3 * cD, 2);

    // 7. LN2
    ln_kernel<<<cM, 256>>>(H2, nullptr, ln2_g, ln2_b, nullptr, HL2, 0);

    // 8. fc = gelu(ln2(h2) @ W_fc + b_fc)
    act_split<<<(cM * cD + 255) / 256, 256>>>(HL2, As, cM * cD, cD);
    w_split<<<dim3(4 * cD / 32, cD / 32), 256>>>(W_fc, Bs, cD, 4 * cD);
    tgemm<<<dim3(4 * cD / 128, 17), 256, TG_SMEM>>>(As, Bs, b_fc, nullptr, FC,
                                                    cM, 4 * cD, 3 * cD, 1);

    // 9. out = (h2 + fc @ W_mproj + b_mproj)[:, 1:, :]
    act_split<<<(cM * 4 * cD + 255) / 256, 256>>>(FC, As, cM * 4 * cD, 4 * cD);
    w_split<<<dim3(cD / 32, 4 * cD / 32), 256>>>(W_mproj, Bs, 4 * cD, cD);
    tgemm<<<dim3(cD / 128, 17), 256, TG_SMEM>>>(As, Bs, b_mproj, H2, out,
                                                cM, cD, 12 * cD, 3);
}